// round 7
// baseline (speedup 1.0000x reference)
#include <cuda_runtime.h>
#include <cstdint>
#include <math.h>

// ---------------------------------------------------------------------------
// VGG-small 1w1a forward, batch 256.
// conv0 fp32 -> stats0 (compensated fp32) -> pack0 (NHWC int8 +-1) ->
// [mma.sync s8 implicit-GEMM bconv -> (pool) -> int stats -> pack] x5 ->
// bn+ht -> fc.  All binary-layer math integer-exact; thresholds exact.
// NOTE: harness compiles to plain sm_103 target -> tcgen05 unavailable;
// int8 mma.sync (IMMA) is the tensor path that works there.
// ---------------------------------------------------------------------------

__device__ __align__(16) float    g_A[33554432];   // conv0 fp32 / int16 NHWC MMA out
__device__ __align__(16) short    g_B[33554432];   // int8 act NHWC / fp32 h
__device__ __align__(16) short    g_C[8388608];    // pooled int16 NHWC
__device__ __align__(16) int8_t   g_Wb[4571136];   // int8 +-1 weights [co][tap][ci]
__device__ long long g_pll[32768];
__device__ float  g_fthr[512];
__device__ int    g_fsgn[512];
__device__ int    g_ithr[512];
__device__ int    g_isgn[512];
__device__ float  g_fsc[512];
__device__ float  g_fsf[512];

// ---------------- compensated fp32 helpers ---------------------------------
__device__ __forceinline__ void two_sum(float& s, float& c, float v) {
  float t = __fadd_rn(s, v);
  float z = __fsub_rn(t, s);
  float e = __fadd_rn(__fsub_rn(s, __fsub_rn(t, z)), __fsub_rn(v, z));
  s = t;
  c = __fadd_rn(c, e);
}

// ---------------- conv0: fp32 3->128, 32x32, pad 1 -------------------------
__global__ __launch_bounds__(256) void conv0_kernel(
    const float* __restrict__ x, const float* __restrict__ w,
    float* __restrict__ out) {
  __shared__ float sW[128 * 27];
  __shared__ float sX[3][3][34];
  int bx = blockIdx.x;
  int y = bx & 31, n = bx >> 5;
  int tid = threadIdx.x;
  for (int i = tid; i < 3456; i += 256) sW[i] = w[i];
  for (int i = tid; i < 3 * 3 * 34; i += 256) {
    int col = i % 34;
    int r = (i / 34) % 3;
    int ci = i / (34 * 3);
    int gy = y - 1 + r, gx = col - 1;
    float v = 0.f;
    if (gy >= 0 && gy < 32 && gx >= 0 && gx < 32)
      v = x[((n * 3 + ci) * 32 + gy) * 32 + gx];
    sX[ci][r][col] = v;
  }
  __syncthreads();
  int co = tid >> 1, xh = tid & 1, x0 = xh * 16;
  float wr[27];
#pragma unroll
  for (int ky = 0; ky < 3; ky++)
#pragma unroll
    for (int kx = 0; kx < 3; kx++)
#pragma unroll
      for (int ci = 0; ci < 3; ci++)
        wr[(ky * 3 + kx) * 3 + ci] = sW[((co * 3 + ci) * 3 + ky) * 3 + kx];
  float a[3][3][3];
#pragma unroll
  for (int r = 0; r < 3; r++)
#pragma unroll
    for (int ci = 0; ci < 3; ci++) {
      a[r][0][ci] = sX[ci][r][x0];
      a[r][1][ci] = sX[ci][r][x0 + 1];
    }
  float* obase = out + (((size_t)n * 128 + co) * 32 + y) * 32;
#pragma unroll
  for (int xi = 0; xi < 16; xi++) {
    int xc = x0 + xi;
#pragma unroll
    for (int r = 0; r < 3; r++)
#pragma unroll
      for (int ci = 0; ci < 3; ci++) a[r][2][ci] = sX[ci][r][xc + 2];
    float acc = 0.f;
#pragma unroll
    for (int ky = 0; ky < 3; ky++)
#pragma unroll
      for (int kx = 0; kx < 3; kx++)
#pragma unroll
        for (int ci = 0; ci < 3; ci++)
          acc = fmaf(a[ky][kx][ci], wr[(ky * 3 + kx) * 3 + ci], acc);
    obase[xc] = acc;
#pragma unroll
    for (int r = 0; r < 3; r++)
#pragma unroll
      for (int ci = 0; ci < 3; ci++) {
        a[r][0][ci] = a[r][1][ci];
        a[r][1][ci] = a[r][2][ci];
      }
  }
}

// ------- layer0 stats: one block per channel + exact fp32 boundary ---------
__global__ __launch_bounds__(256) void stats0_all(
    const float* __restrict__ x, const float* __restrict__ g,
    const float* __restrict__ b, float* __restrict__ fthr,
    int* __restrict__ fsgn) {
  int c = blockIdx.x;
  float s = 0.f, cs = 0.f, ss = 0.f, css = 0.f;
  for (int n = 0; n < 256; n++) {
    const float* p = x + ((size_t)n * 128 + c) * 1024;
    for (int i = threadIdx.x; i < 1024; i += 256) {
      float v = p[i];
      two_sum(s, cs, v);
      float v2 = __fmul_rn(v, v);
      float e2 = __fmaf_rn(v, v, -v2);
      two_sum(ss, css, v2);
      css = __fadd_rn(css, e2);
    }
  }
  __shared__ double sh1[256], sh2[256];
  sh1[threadIdx.x] = (double)s + (double)cs;
  sh2[threadIdx.x] = (double)ss + (double)css;
  __syncthreads();
  for (int o = 128; o > 0; o >>= 1) {
    if (threadIdx.x < o) {
      sh1[threadIdx.x] += sh1[threadIdx.x + o];
      sh2[threadIdx.x] += sh2[threadIdx.x + o];
    }
    __syncthreads();
  }
  if (threadIdx.x == 0) {
    double cnt = 256.0 * 1024.0;
    double mean = sh1[0] / cnt;
    double var = sh2[0] / cnt - mean * mean;
    double sc = (double)g[c] * rsqrt(var + 1e-5);
    double sf = (double)b[c] - mean * sc;
    if (sc > 0.0) {
      float v = (float)(-sf / sc);
      if (!isfinite(v)) v = 0.f;
      if (fma((double)v, sc, sf) >= 0.0) {
        for (int it = 0; it < 64; it++) {
          float d = nextafterf(v, -INFINITY);
          if (fma((double)d, sc, sf) >= 0.0) v = d; else break;
        }
      } else {
        for (int it = 0; it < 64; it++) {
          v = nextafterf(v, INFINITY);
          if (fma((double)v, sc, sf) >= 0.0) break;
        }
      }
      fthr[c] = v;
      fsgn[c] = 1;
    } else if (sc < 0.0) {
      float v = (float)(-sf / sc);
      if (!isfinite(v)) v = 0.f;
      if (fma((double)v, sc, sf) >= 0.0) {
        for (int it = 0; it < 64; it++) {
          float d = nextafterf(v, INFINITY);
          if (fma((double)d, sc, sf) >= 0.0) v = d; else break;
        }
      } else {
        for (int it = 0; it < 64; it++) {
          v = nextafterf(v, -INFINITY);
          if (fma((double)v, sc, sf) >= 0.0) break;
        }
      }
      fthr[c] = v;
      fsgn[c] = 0;
    } else {
      fthr[c] = (sf >= 0.0) ? -INFINITY : INFINITY;
      fsgn[c] = 1;
    }
  }
}

// ------- fused: pack0 (NCHW fp32 -> NHWC int8 +-1) + weight int8 pack ------
__global__ __launch_bounds__(256) void pack0_packw_kernel(
    const float* __restrict__ x, const float* __restrict__ fthr,
    const int* __restrict__ fsgn, int8_t* __restrict__ act,
    const float* __restrict__ w1, const float* __restrict__ w2,
    const float* __restrict__ w3, const float* __restrict__ w4,
    const float* __restrict__ w5, int8_t* __restrict__ wb) {
  const int PACK0_BLOCKS = 32768;
  int tid = threadIdx.x;
  if (blockIdx.x < PACK0_BLOCKS) {
    __shared__ int8_t s[32 * 33];
    int bidx = blockIdx.x;
    int n = bidx >> 7;
    int r = bidx & 127;
    int ct = r >> 5, hwt = r & 31;
    int tx = tid & 31, ty = tid >> 5;
#pragma unroll
    for (int j = 0; j < 4; j++) {
      int c_l = ty + j * 8;
      int c = ct * 32 + c_l;
      int hw = hwt * 32 + tx;
      float v = x[((size_t)(n * 128 + c)) * 1024 + hw];
      bool bit = fsgn[c] ? (v >= fthr[c]) : (v <= fthr[c]);
      s[c_l * 33 + tx] = bit ? 1 : -1;
    }
    __syncthreads();
#pragma unroll
    for (int j = 0; j < 4; j++) {
      int hw_l = ty + j * 8;
      act[((size_t)(n * 1024 + hwt * 32 + hw_l)) * 128 + ct * 32 + tx] =
          s[tx * 33 + hw_l];
    }
  } else {
    int idx = (blockIdx.x - PACK0_BLOCKS) * 256 + tid;
    if (idx >= 4571136) return;
    const float* w;
    int Ci, l;
    if (idx < 147456) { w = w1; Ci = 128; l = idx; }
    else if (idx < 442368) { w = w2; Ci = 128; l = idx - 147456; }
    else if (idx < 1032192) { w = w3; Ci = 256; l = idx - 442368; }
    else if (idx < 2211840) { w = w4; Ci = 256; l = idx - 1032192; }
    else { w = w5; Ci = 512; l = idx - 2211840; }
    int ci = l % Ci;
    int tap = (l / Ci) % 9;
    int co = l / (Ci * 9);
    float v = w[((size_t)co * Ci + ci) * 9 + tap];
    wb[idx] = (v >= 0.f) ? 1 : -1;
  }
}

// ============ int8 mma.sync implicit-GEMM binary conv ======================
__device__ __forceinline__ void mma_s8(int* d, const uint32_t* a,
                                       const uint32_t* b) {
  asm volatile(
      "mma.sync.aligned.m16n8k32.row.col.s32.s8.s8.s32 "
      "{%0,%1,%2,%3}, {%4,%5,%6,%7}, {%8,%9}, {%0,%1,%2,%3};"
      : "+r"(d[0]), "+r"(d[1]), "+r"(d[2]), "+r"(d[3])
      : "r"(a[0]), "r"(a[1]), "r"(a[2]), "r"(a[3]), "r"(b[0]), "r"(b[1]));
}

// Block: 256 thr = 8 warps (4M x 2N).  Tile M=128 pixels, N=128 cout, KC=64.
template <int Ci, int Co, int HW_IMG, int W>
__global__ __launch_bounds__(256) void bmma_kernel(
    const int8_t* __restrict__ act, const int8_t* __restrict__ wb,
    short* __restrict__ out) {
  constexpr int H = HW_IMG / W;
  constexpr int NCH = Ci / 64;
  constexpr int ITERS = 9 * NCH;
  constexpr int COG = Co / 128;
  __shared__ __align__(16) int8_t sA[128 * 64];
  __shared__ __align__(16) int8_t sB[128 * 64];
  int tid = threadIdx.x;
  int bx = blockIdx.x;
  int cog = bx % COG;
  int mt = bx / COG;
  int wid = tid >> 5, lane = tid & 31;
  int wm = wid & 3, wn = wid >> 2;
  // loader assignment: row = tid/2, 32B segment = tid%2
  int lrow = tid >> 1, lseg = tid & 1;
  int pg = mt * 128 + lrow;
  int n = pg / HW_IMG;
  int rem = pg % HW_IMG;
  int py = rem / W, px = rem % W;
  int lf = (lrow >> 1) & 3;
  uint32_t sA_st0 = lrow * 64 + (((lseg * 2 + 0) ^ lf) * 16);
  uint32_t sA_st1 = lrow * 64 + (((lseg * 2 + 1) ^ lf) * 16);
  const int8_t* brow = wb + ((size_t)(cog * 128 + lrow) * 9) * Ci + lseg * 32;

  int acc[2][8][4];
#pragma unroll
  for (int i = 0; i < 2; i++)
#pragma unroll
    for (int j = 0; j < 8; j++)
#pragma unroll
      for (int k = 0; k < 4; k++) acc[i][j][k] = 0;

  for (int kt = 0; kt < ITERS; kt++) {
    int tap = kt / NCH, chunk = kt % NCH;
    int dy = tap / 3 - 1, dx = tap % 3 - 1;
    {
      int yy = py + dy, xx = px + dx;
      bool valid = (yy >= 0) && (yy < H) && (xx >= 0) && (xx < W);
      const uint4* src = reinterpret_cast<const uint4*>(
          act + ((size_t)((n * H + yy) * W + xx)) * Ci + chunk * 64 +
          lseg * 32);
      uint4 v0 = valid ? src[0] : make_uint4(0u, 0u, 0u, 0u);
      uint4 v1 = valid ? src[1] : make_uint4(0u, 0u, 0u, 0u);
      *reinterpret_cast<uint4*>(sA + sA_st0) = v0;
      *reinterpret_cast<uint4*>(sA + sA_st1) = v1;
      const uint4* bs =
          reinterpret_cast<const uint4*>(brow + (size_t)tap * Ci + chunk * 64);
      *reinterpret_cast<uint4*>(sB + sA_st0) = bs[0];
      *reinterpret_cast<uint4*>(sB + sA_st1) = bs[1];
    }
    __syncthreads();
#pragma unroll
    for (int s = 0; s < 2; s++) {
      uint32_t af[2][4], bf[8][2];
      int cq = (lane & 3) * 4;
      int u0 = s * 2, u1 = s * 2 + 1;
#pragma unroll
      for (int mf = 0; mf < 2; mf++) {
        int r0 = wm * 32 + mf * 16 + (lane >> 2);
        int r1 = r0 + 8;
        int f0 = (r0 >> 1) & 3, f1 = (r1 >> 1) & 3;
        af[mf][0] = *reinterpret_cast<const uint32_t*>(
            sA + r0 * 64 + ((u0 ^ f0) * 16) + cq);
        af[mf][1] = *reinterpret_cast<const uint32_t*>(
            sA + r1 * 64 + ((u0 ^ f1) * 16) + cq);
        af[mf][2] = *reinterpret_cast<const uint32_t*>(
            sA + r0 * 64 + ((u1 ^ f0) * 16) + cq);
        af[mf][3] = *reinterpret_cast<const uint32_t*>(
            sA + r1 * 64 + ((u1 ^ f1) * 16) + cq);
      }
#pragma unroll
      for (int nf = 0; nf < 8; nf++) {
        int c0 = wn * 64 + nf * 8 + (lane >> 2);
        int fb = (c0 >> 1) & 3;
        bf[nf][0] = *reinterpret_cast<const uint32_t*>(
            sB + c0 * 64 + ((u0 ^ fb) * 16) + cq);
        bf[nf][1] = *reinterpret_cast<const uint32_t*>(
            sB + c0 * 64 + ((u1 ^ fb) * 16) + cq);
      }
#pragma unroll
      for (int mf = 0; mf < 2; mf++)
#pragma unroll
        for (int nf = 0; nf < 8; nf++) mma_s8(acc[mf][nf], af[mf], bf[nf]);
    }
    __syncthreads();
  }
  // epilogue: s32 -> int16 NHWC
#pragma unroll
  for (int mf = 0; mf < 2; mf++) {
    int r0 = mt * 128 + wm * 32 + mf * 16 + (lane >> 2);
#pragma unroll
    for (int nf = 0; nf < 8; nf++) {
      int col = cog * 128 + wn * 64 + nf * 8 + 2 * (lane & 3);
      uint32_t p0 = ((uint32_t)(uint16_t)(short)acc[mf][nf][0]) |
                    (((uint32_t)(uint16_t)(short)acc[mf][nf][1]) << 16);
      uint32_t p1 = ((uint32_t)(uint16_t)(short)acc[mf][nf][2]) |
                    (((uint32_t)(uint16_t)(short)acc[mf][nf][3]) << 16);
      *reinterpret_cast<uint32_t*>(out + (size_t)r0 * Co + col) = p0;
      *reinterpret_cast<uint32_t*>(out + (size_t)(r0 + 8) * Co + col) = p1;
    }
  }
}

// ---------------- 2x2 maxpool, NHWC int16 ----------------------------------
__global__ __launch_bounds__(256) void pool_nhwc_kernel(
    const short* __restrict__ in, short* __restrict__ out,
    int C, int Ho, int Wo, int total) {
  int idx = blockIdx.x * 256 + threadIdx.x;
  if (idx >= total) return;
  int c = idx % C;
  int t = idx / C;
  int xo = t % Wo;
  t /= Wo;
  int yo = t % Ho;
  int n = t / Ho;
  int Wi = Wo * 2;
  size_t base = ((size_t)((n * Ho * 2 + yo * 2) * Wi + xo * 2)) * C + c;
  int v0 = in[base], v1 = in[base + C];
  int v2 = in[base + (size_t)Wi * C], v3 = in[base + (size_t)Wi * C + C];
  out[idx] = (short)max(max(v0, v1), max(v2, v3));
}

// ------------- NHWC int stats: partial (int64) + finalize ------------------
__global__ __launch_bounds__(256) void stats_nhwc_partial(
    const short* __restrict__ x, long long* __restrict__ pll,
    int C, int PC) {
  int lane = threadIdx.x & 31;
  int wrow = threadIdx.x >> 5;
  int c = blockIdx.x * 32 + lane;
  int chunk = blockIdx.y;
  long long s = 0, ss = 0;
  for (int i = wrow; i < PC; i += 8) {
    int p = chunk * PC + i;
    int v = x[(size_t)p * C + c];
    s += v;
    ss += (long long)(v * v);
  }
  __shared__ long long sh1[8][32], sh2[8][32];
  sh1[wrow][lane] = s;
  sh2[wrow][lane] = ss;
  __syncthreads();
  if (wrow == 0) {
    long long S = 0, SS = 0;
#pragma unroll
    for (int r = 0; r < 8; r++) {
      S += sh1[r][lane];
      SS += sh2[r][lane];
    }
    pll[c * 32 + chunk] = S;
    pll[16384 + c * 32 + chunk] = SS;
  }
}

__global__ void stats_nhwc_fin(const long long* __restrict__ pll,
                               const float* __restrict__ g,
                               const float* __restrict__ b,
                               int* __restrict__ thr, int* __restrict__ sgn,
                               float* __restrict__ fsc, float* __restrict__ fsf,
                               int C, double cnt) {
  int c = blockIdx.x * blockDim.x + threadIdx.x;
  if (c >= C) return;
  long long S = 0, SS = 0;
  for (int ch = 0; ch < 32; ch++) {
    S += pll[c * 32 + ch];
    SS += pll[16384 + c * 32 + ch];
  }
  double mean = (double)S / cnt;
  double var = (double)SS / cnt - mean * mean;
  double sc = (double)g[c] * rsqrt(var + 1e-5);
  double sf = (double)b[c] - mean * sc;
  fsc[c] = (float)sc;
  fsf[c] = (float)sf;
  double T = -sf / sc;
  if (sc > 0.0) {
    thr[c] = (int)ceil(T);
    sgn[c] = 1;
  } else {
    thr[c] = (int)floor(T);
    sgn[c] = 0;
  }
}

// ------------- NHWC pack: int16 -> int8 +-1 --------------------------------
__global__ __launch_bounds__(256) void pack_nhwc_kernel(
    const short* __restrict__ x, const int* __restrict__ thr,
    const int* __restrict__ sgn, int8_t* __restrict__ act,
    int C, int total) {
  int idx = blockIdx.x * 256 + threadIdx.x;
  if (idx >= total) return;
  int c = idx & (C - 1);
  int v = x[idx];
  bool bit = sgn[c] ? (v >= thr[c]) : (v <= thr[c]);
  act[idx] = bit ? 1 : -1;
}

// ------------- bn + hardtanh: NHWC int16 -> NCHW fp32 ----------------------
__global__ __launch_bounds__(256) void bn_ht_kernel(
    const short* __restrict__ in, const float* __restrict__ fsc,
    const float* __restrict__ fsf, float* __restrict__ out, int total) {
  int idx = blockIdx.x * 256 + threadIdx.x;
  if (idx >= total) return;
  int hw = idx & 15;
  int c = (idx >> 4) & 511;
  int n = idx >> 13;
  int v = in[((size_t)(n * 16 + hw)) * 512 + c];
  float z = fmaf((float)v, fsc[c], fsf[c]);
  out[idx] = fminf(1.f, fmaxf(-1.f, z));
}

// ----- FC: [256,8192] @ [10,8192]^T + b (TwoProd+Neumaier fp32) ------------
__global__ __launch_bounds__(256) void fc_kernel(
    const float* __restrict__ h, const float* __restrict__ wfc,
    const float* __restrict__ bfc, float* __restrict__ out) {
  int gtid = blockIdx.x * blockDim.x + threadIdx.x;
  int warp = gtid >> 5;
  int lane = gtid & 31;
  if (warp >= 256 * 10) return;
  int n = warp / 10, k = warp % 10;
  const float* hp = h + (size_t)n * 8192;
  const float* wp = wfc + (size_t)k * 8192;
  float s = 0.f, c = 0.f;
  for (int j = lane; j < 8192; j += 32) {
    float a = hp[j], b = wp[j];
    float p = __fmul_rn(a, b);
    float e = __fmaf_rn(a, b, -p);
    two_sum(s, c, p);
    c = __fadd_rn(c, e);
  }
  double d = (double)s + (double)c;
#pragma unroll
  for (int o = 16; o > 0; o >>= 1) d += __shfl_xor_sync(0xFFFFFFFFu, d, o);
  if (lane == 0) out[n * 10 + k] = (float)(d + (double)bfc[k]);
}

// ---------------------------------------------------------------------------
static inline int cdiv(int a, int b) { return (a + b - 1) / b; }

extern "C" void kernel_launch(void* const* d_in, const int* in_sizes, int n_in,
                              void* d_out, int out_size) {
  const float* x   = (const float*)d_in[0];
  const float* w0_ = (const float*)d_in[1];
  const float* g0  = (const float*)d_in[2];
  const float* b0  = (const float*)d_in[3];
  const float* wc1 = (const float*)d_in[4];
  const float* g1  = (const float*)d_in[5];
  const float* b1  = (const float*)d_in[6];
  const float* wc2 = (const float*)d_in[7];
  const float* g2  = (const float*)d_in[8];
  const float* b2  = (const float*)d_in[9];
  const float* wc3 = (const float*)d_in[10];
  const float* g3  = (const float*)d_in[11];
  const float* b3  = (const float*)d_in[12];
  const float* wc4 = (const float*)d_in[13];
  const float* g4  = (const float*)d_in[14];
  const float* b4  = (const float*)d_in[15];
  const float* wc5 = (const float*)d_in[16];
  const float* g5  = (const float*)d_in[17];
  const float* b5  = (const float*)d_in[18];
  const float* wfc = (const float*)d_in[19];
  const float* bfc = (const float*)d_in[20];
  float* out = (float*)d_out;

  float *A, *fsc, *fsf, *fthr;
  short *B, *Cc;
  int8_t* Wb;
  long long* pll;
  int *thr, *sgn, *fsgn;
  cudaGetSymbolAddress((void**)&A, g_A);
  cudaGetSymbolAddress((void**)&B, g_B);
  cudaGetSymbolAddress((void**)&Cc, g_C);
  cudaGetSymbolAddress((void**)&Wb, g_Wb);
  cudaGetSymbolAddress((void**)&pll, g_pll);
  cudaGetSymbolAddress((void**)&fthr, g_fthr);
  cudaGetSymbolAddress((void**)&fsgn, g_fsgn);
  cudaGetSymbolAddress((void**)&thr, g_ithr);
  cudaGetSymbolAddress((void**)&sgn, g_isgn);
  cudaGetSymbolAddress((void**)&fsc, g_fsc);
  cudaGetSymbolAddress((void**)&fsf, g_fsf);
  short* As = (short*)A;
  int8_t* act = (int8_t*)B;
  float* hbuf = (float*)B;

  const int TB = 256;

  // 0: conv0 (fp32 NCHW -> g_A)
  conv0_kernel<<<256 * 32, TB>>>(x, w0_, A);
  // 1: bn0 stats + exact fp32 boundary
  stats0_all<<<128, TB>>>(A, g0, b0, fthr, fsgn);
  // 2: pack0 (NHWC int8 act -> g_B) + all weights -> int8 (g_Wb)
  pack0_packw_kernel<<<32768 + cdiv(4571136, TB), TB>>>(
      A, fthr, fsgn, act, wc1, wc2, wc3, wc4, wc5, Wb);

  // 3: conv1 MMA 128->128 @32x32   (profiled slot)
  bmma_kernel<128, 128, 1024, 32><<<2048, TB>>>(act, Wb + 0, As);
  pool_nhwc_kernel<<<cdiv(65536 * 128, TB), TB>>>(As, Cc, 128, 16, 16,
                                                  65536 * 128);
  stats_nhwc_partial<<<dim3(4, 32), TB>>>(Cc, pll, 128, 2048);
  stats_nhwc_fin<<<1, 128>>>(pll, g1, b1, thr, sgn, fsc, fsf, 128, 65536.0);
  pack_nhwc_kernel<<<cdiv(65536 * 128, TB), TB>>>(Cc, thr, sgn, act, 128,
                                                  65536 * 128);

  // conv2 MMA 128->256 @16x16
  bmma_kernel<128, 256, 256, 16><<<1024, TB>>>(act, Wb + 147456, As);
  stats_nhwc_partial<<<dim3(8, 32), TB>>>(As, pll, 256, 2048);
  stats_nhwc_fin<<<1, 256>>>(pll, g2, b2, thr, sgn, fsc, fsf, 256, 65536.0);
  pack_nhwc_kernel<<<cdiv(65536 * 256, TB), TB>>>(As, thr, sgn, act, 256,
                                                  65536 * 256);

  // conv3 MMA 256->256 @16x16 + pool -> 8x8
  bmma_kernel<256, 256, 256, 16><<<1024, TB>>>(act, Wb + 442368, As);
  pool_nhwc_kernel<<<cdiv(16384 * 256, TB), TB>>>(As, Cc, 256, 8, 8,
                                                  16384 * 256);
  stats_nhwc_partial<<<dim3(8, 32), TB>>>(Cc, pll, 256, 512);
  stats_nhwc_fin<<<1, 256>>>(pll, g3, b3, thr, sgn, fsc, fsf, 256, 16384.0);
  pack_nhwc_kernel<<<cdiv(16384 * 256, TB), TB>>>(Cc, thr, sgn, act, 256,
                                                  16384 * 256);

  // conv4 MMA 256->512 @8x8
  bmma_kernel<256, 512, 64, 8><<<512, TB>>>(act, Wb + 1032192, As);
  stats_nhwc_partial<<<dim3(16, 32), TB>>>(As, pll, 512, 512);
  stats_nhwc_fin<<<2, 256>>>(pll, g4, b4, thr, sgn, fsc, fsf, 512, 16384.0);
  pack_nhwc_kernel<<<cdiv(16384 * 512, TB), TB>>>(As, thr, sgn, act, 512,
                                                  16384 * 512);

  // conv5 MMA 512->512 @8x8 + pool -> 4x4
  bmma_kernel<512, 512, 64, 8><<<512, TB>>>(act, Wb + 2211840, As);
  pool_nhwc_kernel<<<cdiv(4096 * 512, TB), TB>>>(As, Cc, 512, 4, 4,
                                                 4096 * 512);
  stats_nhwc_partial<<<dim3(16, 32), TB>>>(Cc, pll, 512, 128);
  stats_nhwc_fin<<<2, 256>>>(pll, g5, b5, thr, sgn, fsc, fsf, 512, 4096.0);

  // bn5 + hardtanh (NHWC -> NCHW fp32 h in g_B), then FC
  bn_ht_kernel<<<cdiv(2097152, TB), TB>>>(Cc, fsc, fsf, hbuf, 2097152);
  fc_kernel<<<cdiv(256 * 10 * 32, TB), TB>>>(hbuf, wfc, bfc, out);
}

// round 8
// speedup vs baseline: 1.0217x; 1.0217x over previous
#include <cuda_runtime.h>
#include <cstdint>
#include <math.h>

// ---------------------------------------------------------------------------
// VGG-small 1w1a forward, batch 256.  HYBRID round:
// Each binary conv layer = ONE kernel whose blocks are split between
//   - popcount path (ALU pipe)  : n in [nI, 256), bitpacked XNOR+popc
//   - IMMA path (tensor pipe)   : n in [0, nI),  legacy mma.sync s8
// interleaved proportionally so both pipes run concurrently on every SM.
// Both paths write identical int16 NCHW (exact even integers).
// ---------------------------------------------------------------------------

__device__ __align__(16) float    g_A[33554432];   // conv int16 NCHW / final h fp32
__device__ __align__(16) short    g_C[8388608];    // pooled int16 NCHW
__device__ __align__(16) uint32_t g_P[1048576];    // bitpacked act [pixel][C/32]
__device__ __align__(16) int8_t   g_P8[33554432];  // int8 act NHWC [pixel][C]
__device__ __align__(16) uint32_t g_Wp[142848];    // bitpacked weights
__device__ __align__(16) int8_t   g_Wb[4571136];   // int8 weights [co][tap][ci]
__device__ float  g_fthr[512];
__device__ int    g_fsgn[512];
__device__ int    g_ithr[512];
__device__ int    g_isgn[512];
__device__ float  g_fsc[512];
__device__ float  g_fsf[512];

// ---------------- compensated fp32 helpers ---------------------------------
__device__ __forceinline__ void two_sum(float& s, float& c, float v) {
  float t = __fadd_rn(s, v);
  float z = __fsub_rn(t, s);
  float e = __fadd_rn(__fsub_rn(s, __fsub_rn(t, z)), __fsub_rn(v, z));
  s = t;
  c = __fadd_rn(c, e);
}

// ---------------- conv0: fp32 3->128, 32x32, pad 1 -------------------------
__global__ __launch_bounds__(256) void conv0_kernel(
    const float* __restrict__ x, const float* __restrict__ w,
    float* __restrict__ out) {
  __shared__ float sW[128 * 27];
  __shared__ float sX[3][3][34];
  int bx = blockIdx.x;
  int y = bx & 31, n = bx >> 5;
  int tid = threadIdx.x;
  for (int i = tid; i < 3456; i += 256) sW[i] = w[i];
  for (int i = tid; i < 3 * 3 * 34; i += 256) {
    int col = i % 34;
    int r = (i / 34) % 3;
    int ci = i / (34 * 3);
    int gy = y - 1 + r, gx = col - 1;
    float v = 0.f;
    if (gy >= 0 && gy < 32 && gx >= 0 && gx < 32)
      v = x[((n * 3 + ci) * 32 + gy) * 32 + gx];
    sX[ci][r][col] = v;
  }
  __syncthreads();
  int co = tid >> 1, xh = tid & 1, x0 = xh * 16;
  float wr[27];
#pragma unroll
  for (int ky = 0; ky < 3; ky++)
#pragma unroll
    for (int kx = 0; kx < 3; kx++)
#pragma unroll
      for (int ci = 0; ci < 3; ci++)
        wr[(ky * 3 + kx) * 3 + ci] = sW[((co * 3 + ci) * 3 + ky) * 3 + kx];
  float a[3][3][3];
#pragma unroll
  for (int r = 0; r < 3; r++)
#pragma unroll
    for (int ci = 0; ci < 3; ci++) {
      a[r][0][ci] = sX[ci][r][x0];
      a[r][1][ci] = sX[ci][r][x0 + 1];
    }
  float* obase = out + (((size_t)n * 128 + co) * 32 + y) * 32;
#pragma unroll
  for (int xi = 0; xi < 16; xi++) {
    int xc = x0 + xi;
#pragma unroll
    for (int r = 0; r < 3; r++)
#pragma unroll
      for (int ci = 0; ci < 3; ci++) a[r][2][ci] = sX[ci][r][xc + 2];
    float acc = 0.f;
#pragma unroll
    for (int ky = 0; ky < 3; ky++)
#pragma unroll
      for (int kx = 0; kx < 3; kx++)
#pragma unroll
        for (int ci = 0; ci < 3; ci++)
          acc = fmaf(a[ky][kx][ci], wr[(ky * 3 + kx) * 3 + ci], acc);
    obase[xc] = acc;
#pragma unroll
    for (int r = 0; r < 3; r++)
#pragma unroll
      for (int ci = 0; ci < 3; ci++) {
        a[r][0][ci] = a[r][1][ci];
        a[r][1][ci] = a[r][2][ci];
      }
  }
}

// ------- layer0 stats: one block per channel + exact fp32 boundary ---------
__global__ __launch_bounds__(256) void stats0_all(
    const float* __restrict__ x, const float* __restrict__ g,
    const float* __restrict__ b, float* __restrict__ fthr,
    int* __restrict__ fsgn) {
  int c = blockIdx.x;
  float s = 0.f, cs = 0.f, ss = 0.f, css = 0.f;
  for (int n = 0; n < 256; n++) {
    const float* p = x + ((size_t)n * 128 + c) * 1024;
    for (int i = threadIdx.x; i < 1024; i += 256) {
      float v = p[i];
      two_sum(s, cs, v);
      float v2 = __fmul_rn(v, v);
      float e2 = __fmaf_rn(v, v, -v2);
      two_sum(ss, css, v2);
      css = __fadd_rn(css, e2);
    }
  }
  __shared__ double sh1[256], sh2[256];
  sh1[threadIdx.x] = (double)s + (double)cs;
  sh2[threadIdx.x] = (double)ss + (double)css;
  __syncthreads();
  for (int o = 128; o > 0; o >>= 1) {
    if (threadIdx.x < o) {
      sh1[threadIdx.x] += sh1[threadIdx.x + o];
      sh2[threadIdx.x] += sh2[threadIdx.x + o];
    }
    __syncthreads();
  }
  if (threadIdx.x == 0) {
    double cnt = 256.0 * 1024.0;
    double mean = sh1[0] / cnt;
    double var = sh2[0] / cnt - mean * mean;
    double sc = (double)g[c] * rsqrt(var + 1e-5);
    double sf = (double)b[c] - mean * sc;
    if (sc > 0.0) {
      float v = (float)(-sf / sc);
      if (!isfinite(v)) v = 0.f;
      if (fma((double)v, sc, sf) >= 0.0) {
        for (int it = 0; it < 64; it++) {
          float d = nextafterf(v, -INFINITY);
          if (fma((double)d, sc, sf) >= 0.0) v = d; else break;
        }
      } else {
        for (int it = 0; it < 64; it++) {
          v = nextafterf(v, INFINITY);
          if (fma((double)v, sc, sf) >= 0.0) break;
        }
      }
      fthr[c] = v;
      fsgn[c] = 1;
    } else if (sc < 0.0) {
      float v = (float)(-sf / sc);
      if (!isfinite(v)) v = 0.f;
      if (fma((double)v, sc, sf) >= 0.0) {
        for (int it = 0; it < 64; it++) {
          float d = nextafterf(v, INFINITY);
          if (fma((double)d, sc, sf) >= 0.0) v = d; else break;
        }
      } else {
        for (int it = 0; it < 64; it++) {
          v = nextafterf(v, -INFINITY);
          if (fma((double)v, sc, sf) >= 0.0) break;
        }
      }
      fthr[c] = v;
      fsgn[c] = 0;
    } else {
      fthr[c] = (sf >= 0.0) ? -INFINITY : INFINITY;
      fsgn[c] = 1;
    }
  }
}

// ---- pack_all: layer0 act (int8 NHWC + bitpack) + weights (both formats) --
__global__ __launch_bounds__(256) void pack_all_kernel(
    const float* __restrict__ x, const float* __restrict__ fthr,
    const int* __restrict__ fsgn, int8_t* __restrict__ act8,
    uint32_t* __restrict__ apk,
    const float* __restrict__ w1, const float* __restrict__ w2,
    const float* __restrict__ w3, const float* __restrict__ w4,
    const float* __restrict__ w5, uint32_t* __restrict__ wpk,
    int8_t* __restrict__ wb8) {
  const int R0 = 32768, R1 = R0 + 4096, R2 = R1 + 558;
  int tid = threadIdx.x;
  int bx = blockIdx.x;
  if (bx < R0) {
    // transpose NCHW fp32 -> NHWC int8
    __shared__ int8_t s[32 * 33];
    int n = bx >> 7;
    int r = bx & 127;
    int ct = r >> 5, hwt = r & 31;
    int tx = tid & 31, ty = tid >> 5;
#pragma unroll
    for (int j = 0; j < 4; j++) {
      int c_l = ty + j * 8;
      int c = ct * 32 + c_l;
      int hw = hwt * 32 + tx;
      float v = x[((size_t)(n * 128 + c)) * 1024 + hw];
      bool bit = fsgn[c] ? (v >= fthr[c]) : (v <= fthr[c]);
      s[c_l * 33 + tx] = bit ? 1 : -1;
    }
    __syncthreads();
#pragma unroll
    for (int j = 0; j < 4; j++) {
      int hw_l = ty + j * 8;
      act8[((size_t)(n * 1024 + hwt * 32 + hw_l)) * 128 + ct * 32 + tx] =
          s[tx * 33 + hw_l];
    }
  } else if (bx < R1) {
    // bitpack layer0 act: [pixel][4]
    int gt = (bx - R0) * 256 + tid;
    int lane = gt & 31;
    int gw = gt >> 5;
    int wrd = gw & 3;
    int pixel = (gw >> 2) * 32 + lane;
    int n = pixel >> 10, hw = pixel & 1023;
    const float* base = x + ((size_t)(n * 128 + wrd * 32)) * 1024 + hw;
    const float* tp = fthr + wrd * 32;
    const int* sp = fsgn + wrd * 32;
    uint32_t bits = 0;
#pragma unroll 8
    for (int k = 0; k < 32; k++) {
      float v = base[(size_t)k * 1024];
      bool bit = sp[k] ? (v >= tp[k]) : (v <= tp[k]);
      bits |= (bit ? 1u : 0u) << k;
    }
    apk[(size_t)pixel * 4 + wrd] = bits;
  } else if (bx < R2) {
    // weight bitpack [co][tap][Ci/32]
    int idx = (bx - R1) * 256 + tid;
    if (idx >= 142848) return;
    const float* w;
    int Ci, l;
    if (idx < 4608) { w = w1; Ci = 128; l = idx; }
    else if (idx < 13824) { w = w2; Ci = 128; l = idx - 4608; }
    else if (idx < 32256) { w = w3; Ci = 256; l = idx - 13824; }
    else if (idx < 69120) { w = w4; Ci = 256; l = idx - 32256; }
    else { w = w5; Ci = 512; l = idx - 69120; }
    int NW = Ci >> 5;
    int wrd = l % NW;
    int t = l / NW;
    int tap = t % 9;
    int co = t / 9;
    uint32_t bits = 0;
#pragma unroll 8
    for (int k = 0; k < 32; k++) {
      float v = w[((size_t)co * Ci + (wrd * 32 + k)) * 9 + tap];
      bits |= (v >= 0.f ? 1u : 0u) << k;
    }
    wpk[idx] = bits;
  } else {
    // weight int8 [co][tap][ci]
    int idx = (bx - R2) * 256 + tid;
    if (idx >= 4571136) return;
    const float* w;
    int Ci, l;
    if (idx < 147456) { w = w1; Ci = 128; l = idx; }
    else if (idx < 442368) { w = w2; Ci = 128; l = idx - 147456; }
    else if (idx < 1032192) { w = w3; Ci = 256; l = idx - 442368; }
    else if (idx < 2211840) { w = w4; Ci = 256; l = idx - 1032192; }
    else { w = w5; Ci = 512; l = idx - 2211840; }
    int ci = l % Ci;
    int tap = (l / Ci) % 9;
    int co = l / (Ci * 9);
    float v = w[((size_t)co * Ci + ci) * 9 + tap];
    wb8[idx] = (v >= 0.f) ? 1 : -1;
  }
}

// ============ hybrid binary conv: popcount blocks + IMMA blocks ============
__device__ __forceinline__ int popc4(uint4 a, uint4 b) {
  return __popc(a.x ^ b.x) + __popc(a.y ^ b.y) +
         __popc(a.z ^ b.z) + __popc(a.w ^ b.w);
}
__device__ __forceinline__ void mma_s8(int* d, const uint32_t* a,
                                       const uint32_t* b) {
  asm volatile(
      "mma.sync.aligned.m16n8k32.row.col.s32.s8.s8.s32 "
      "{%0,%1,%2,%3}, {%4,%5,%6,%7}, {%8,%9}, {%0,%1,%2,%3};"
      : "+r"(d[0]), "+r"(d[1]), "+r"(d[2]), "+r"(d[3])
      : "r"(a[0]), "r"(a[1]), "r"(a[2]), "r"(a[3]), "r"(b[0]), "r"(b[1]));
}

template <int Ci, int Co, int H, int W, int CO_G, int NW, int SPLIT, int YT,
          int XT, bool POOL>
__global__ __launch_bounds__(256, 2) void hybrid_kernel(
    const uint32_t* __restrict__ apk, const uint32_t* __restrict__ wpk,
    const int8_t* __restrict__ act8, const int8_t* __restrict__ wb8,
    short* __restrict__ out, int Gi, int Gtot, int nI) {
  constexpr int HW = H * W;
  constexpr int HWo = HW / 4;
  constexpr int Wo = W / 2;
  constexpr int POPW = CO_G * 9 * NW * 4;
  constexpr int POPBYTES = POPW + (YT + 2) * W * NW * 4;
  constexpr int UNION = (POPBYTES > 33280) ? POPBYTES : 33280;
  __shared__ __align__(16) unsigned char smraw[UNION];
  int tid = threadIdx.x;
  long long t1 = ((long long)blockIdx.x * Gi) / Gtot;
  long long t2 = ((long long)(blockIdx.x + 1) * Gi) / Gtot;
  if (t2 > t1) {
    // ======================= IMMA path (tensor pipe) =======================
    int ir = (int)t1;
    constexpr int COG = Co / 128;
    constexpr int NCH = Ci / 64;
    constexpr int ITERS = 9 * NCH;
    int cog = ir % COG;
    int mt = ir / COG;
    int8_t* sA = (int8_t*)smraw;
    int8_t* sB = (int8_t*)(smraw + 8192);
    int wid = tid >> 5, lane = tid & 31;
    int wm = wid & 3, wn = wid >> 2;
    int lrow = tid >> 1, lseg = tid & 1;
    int pg = mt * 128 + lrow;
    int n = pg / HW;
    int rem = pg % HW;
    int py = rem / W, px = rem % W;
    int lf = (lrow >> 1) & 3;
    uint32_t st0 = lrow * 64 + (((lseg * 2 + 0) ^ lf) * 16);
    uint32_t st1 = lrow * 64 + (((lseg * 2 + 1) ^ lf) * 16);
    const int8_t* brow =
        wb8 + ((size_t)(cog * 128 + lrow) * 9) * Ci + lseg * 32;
    int acc[2][8][4];
#pragma unroll
    for (int i = 0; i < 2; i++)
#pragma unroll
      for (int j = 0; j < 8; j++)
#pragma unroll
        for (int k = 0; k < 4; k++) acc[i][j][k] = 0;
    for (int kt = 0; kt < ITERS; kt++) {
      int tap = kt / NCH, chunk = kt % NCH;
      int dy = tap / 3 - 1, dx = tap % 3 - 1;
      {
        int yy = py + dy, xx = px + dx;
        bool valid = (yy >= 0) && (yy < H) && (xx >= 0) && (xx < W);
        const uint4* src = reinterpret_cast<const uint4*>(
            act8 + ((size_t)((n * H + yy) * W + xx)) * Ci + chunk * 64 +
            lseg * 32);
        uint4 v0 = valid ? src[0] : make_uint4(0u, 0u, 0u, 0u);
        uint4 v1 = valid ? src[1] : make_uint4(0u, 0u, 0u, 0u);
        *reinterpret_cast<uint4*>(sA + st0) = v0;
        *reinterpret_cast<uint4*>(sA + st1) = v1;
        const uint4* bs = reinterpret_cast<const uint4*>(
            brow + (size_t)tap * Ci + chunk * 64);
        *reinterpret_cast<uint4*>(sB + st0) = bs[0];
        *reinterpret_cast<uint4*>(sB + st1) = bs[1];
      }
      __syncthreads();
#pragma unroll
      for (int s = 0; s < 2; s++) {
        uint32_t af[2][4], bf[8][2];
        int cq = (lane & 3) * 4;
        int u0 = s * 2, u1 = s * 2 + 1;
#pragma unroll
        for (int mf = 0; mf < 2; mf++) {
          int r0 = wm * 32 + mf * 16 + (lane >> 2);
          int r1 = r0 + 8;
          int f0 = (r0 >> 1) & 3, f1 = (r1 >> 1) & 3;
          af[mf][0] = *reinterpret_cast<const uint32_t*>(
              sA + r0 * 64 + ((u0 ^ f0) * 16) + cq);
          af[mf][1] = *reinterpret_cast<const uint32_t*>(
              sA + r1 * 64 + ((u0 ^ f1) * 16) + cq);
          af[mf][2] = *reinterpret_cast<const uint32_t*>(
              sA + r0 * 64 + ((u1 ^ f0) * 16) + cq);
          af[mf][3] = *reinterpret_cast<const uint32_t*>(
              sA + r1 * 64 + ((u1 ^ f1) * 16) + cq);
        }
#pragma unroll
        for (int nf = 0; nf < 8; nf++) {
          int c0 = wn * 64 + nf * 8 + (lane >> 2);
          int fb = (c0 >> 1) & 3;
          bf[nf][0] = *reinterpret_cast<const uint32_t*>(
              sB + c0 * 64 + ((u0 ^ fb) * 16) + cq);
          bf[nf][1] = *reinterpret_cast<const uint32_t*>(
              sB + c0 * 64 + ((u1 ^ fb) * 16) + cq);
        }
#pragma unroll
        for (int mf = 0; mf < 2; mf++)
#pragma unroll
          for (int nf = 0; nf < 8; nf++) mma_s8(acc[mf][nf], af[mf], bf[nf]);
      }
      __syncthreads();
    }
    // epilogue: stage int16 tile [pixel][co] (pitch 130), pool, NCHW write
    short* staged = (short*)smraw;
#pragma unroll
    for (int mf = 0; mf < 2; mf++) {
      int r0 = wm * 32 + mf * 16 + (lane >> 2);
#pragma unroll
      for (int nf = 0; nf < 8; nf++) {
        int col = wn * 64 + nf * 8 + 2 * (lane & 3);
        uint32_t p0 = ((uint32_t)(uint16_t)(short)acc[mf][nf][0]) |
                      (((uint32_t)(uint16_t)(short)acc[mf][nf][1]) << 16);
        uint32_t p1 = ((uint32_t)(uint16_t)(short)acc[mf][nf][2]) |
                      (((uint32_t)(uint16_t)(short)acc[mf][nf][3]) << 16);
        *reinterpret_cast<uint32_t*>(&staged[r0 * 130 + col]) = p0;
        *reinterpret_cast<uint32_t*>(&staged[(r0 + 8) * 130 + col]) = p1;
      }
    }
    __syncthreads();
    if (POOL) {
      for (int col = wid; col < 128; col += 8) {
        int yo = lane / Wo, xo = lane % Wo;
        int p00 = (2 * yo) * W + 2 * xo;
        int a0 = staged[p00 * 130 + col];
        int a1 = staged[(p00 + 1) * 130 + col];
        int a2 = staged[(p00 + W) * 130 + col];
        int a3 = staged[(p00 + W + 1) * 130 + col];
        short m = (short)max(max(a0, a1), max(a2, a3));
        int pgo = mt * 32 + lane;
        int n2 = pgo / HWo, hwo = pgo % HWo;
        out[((size_t)n2 * Co + cog * 128 + col) * HWo + hwo] = m;
      }
    } else {
      for (int col = wid; col < 128; col += 8) {
#pragma unroll
        for (int it = 0; it < 4; it++) {
          int p = it * 32 + lane;
          short val = staged[p * 130 + col];
          int pg2 = mt * 128 + p;
          int n2 = pg2 / HW, hw2 = pg2 % HW;
          out[((size_t)n2 * Co + cog * 128 + col) * HW + hw2] = val;
        }
      }
    }
  } else {
    // ==================== popcount path (ALU pipe) =========================
    int pr = blockIdx.x - (int)t1;
    constexpr int CGRP = Co / CO_G;
    uint32_t* sW = reinterpret_cast<uint32_t*>(smraw);
    uint32_t* sAp = reinterpret_cast<uint32_t*>(smraw + POPW);
    int cg = pr % CGRP;
    int yg = (pr / CGRP) % (H / YT);
    int n = nI + pr / (CGRP * (H / YT));
    const uint4* wsrc =
        reinterpret_cast<const uint4*>(wpk + (size_t)cg * CO_G * 9 * NW);
    for (int i = tid; i < CO_G * 9 * NW / 4; i += 256)
      reinterpret_cast<uint4*>(sW)[i] = wsrc[i];
    int ybase = yg * YT;
    constexpr int RW4 = W * NW / 4;
    for (int i = tid; i < (YT + 2) * RW4; i += 256) {
      int r = i / RW4;
      int gy = ybase - 1 + r;
      uint4 v = make_uint4(0u, 0u, 0u, 0u);
      if (gy >= 0 && gy < H)
        v = reinterpret_cast<const uint4*>(
            apk + ((size_t)(n * H + gy) * W) * NW)[i % RW4];
      reinterpret_cast<uint4*>(sAp)[i] = v;
    }
    __syncthreads();
    int slice = tid % SPLIT;
    int tt = tid / SPLIT;
    int xg = tt % (W / XT);
    int co_l = tt / (W / XT);
    int x0 = xg * XT;
    uint4 wt[9];
#pragma unroll
    for (int t = 0; t < 9; t++)
      wt[t] = *reinterpret_cast<const uint4*>(
          &sW[(co_l * 9 + t) * NW + slice * 4]);
    int co = cg * CO_G + co_l;
    int pmax[XT / 2];
    int tmpv = 0;
#pragma unroll
    for (int ry = 0; ry < YT; ry++) {
      int y = ybase + ry;
      int rv0 = (y > 0) ? 1 : 0;
      int rv2 = (y < H - 1) ? 1 : 0;
      int nrows = 1 + rv0 + rv2;
      uint4 aL[3], aM[3], aR[3];
#pragma unroll
      for (int rr = 0; rr < 3; rr++) {
        aM[rr] = *reinterpret_cast<const uint4*>(
            &sAp[((ry + rr) * W + x0) * NW + slice * 4]);
        aL[rr] = (x0 > 0)
                     ? *reinterpret_cast<const uint4*>(
                           &sAp[((ry + rr) * W + x0 - 1) * NW + slice * 4])
                     : make_uint4(0u, 0u, 0u, 0u);
      }
#pragma unroll
      for (int xi = 0; xi < XT; xi++) {
        int xc = x0 + xi;
        int cl = (xc > 0) ? 1 : 0;
        int cr = (xc < W - 1) ? 1 : 0;
#pragma unroll
        for (int rr = 0; rr < 3; rr++)
          aR[rr] = cr ? *reinterpret_cast<const uint4*>(
                            &sAp[((ry + rr) * W + xc + 1) * NW + slice * 4])
                      : make_uint4(0u, 0u, 0u, 0u);
        int cnt = 0;
#pragma unroll
        for (int rr = 0; rr < 3; rr++) {
          int rvalid = (rr == 0) ? rv0 : ((rr == 2) ? rv2 : 1);
          if (rvalid) {
            if (cl) cnt += popc4(aL[rr], wt[rr * 3 + 0]);
            cnt += popc4(aM[rr], wt[rr * 3 + 1]);
            if (cr) cnt += popc4(aR[rr], wt[rr * 3 + 2]);
          }
        }
#pragma unroll
        for (int o = 1; o < SPLIT; o <<= 1)
          cnt += __shfl_xor_sync(0xffffffffu, cnt, o);
        int ncols = 1 + cl + cr;
        int val = nrows * ncols * 32 * NW - 2 * cnt;
        if (POOL) {
          if ((xi & 1) == 0) {
            tmpv = val;
          } else {
            int m2 = max(tmpv, val);
            if ((ry & 1) == 0) {
              pmax[xi >> 1] = m2;
            } else {
              int m = max(pmax[xi >> 1], m2);
              if (slice == 0)
                out[(((size_t)n * Co + co) * (H / 2) + (y >> 1)) * (W / 2) +
                    (xc >> 1)] = (short)m;
            }
          }
        } else {
          if (slice == 0)
            out[(((size_t)n * Co + co) * H + y) * W + xc] = (short)val;
        }
#pragma unroll
        for (int rr = 0; rr < 3; rr++) {
          aL[rr] = aM[rr];
          aM[rr] = aR[rr];
        }
      }
    }
  }
}

// -------- binary-layer stats: exact int64 accumulation (NCHW) --------------
__global__ __launch_bounds__(256) void stats_int_kernel(
    const short* __restrict__ x, const float* __restrict__ g,
    const float* __restrict__ b, float* __restrict__ fsc,
    float* __restrict__ fsf, int* __restrict__ thr, int* __restrict__ sgn,
    int N, int C, int HW) {
  int c = blockIdx.x;
  long long s = 0, ss = 0;
  for (int n = 0; n < N; n++) {
    const short* p = x + ((size_t)n * C + c) * HW;
    for (int i = threadIdx.x; i < HW; i += 256) {
      int v = p[i];
      s += v;
      ss += (long long)(v * v);
    }
  }
  __shared__ long long sh1[256], sh2[256];
  sh1[threadIdx.x] = s;
  sh2[threadIdx.x] = ss;
  __syncthreads();
  for (int o = 128; o > 0; o >>= 1) {
    if (threadIdx.x < o) {
      sh1[threadIdx.x] += sh1[threadIdx.x + o];
      sh2[threadIdx.x] += sh2[threadIdx.x + o];
    }
    __syncthreads();
  }
  if (threadIdx.x == 0) {
    double cnt = (double)N * (double)HW;
    double mean = (double)sh1[0] / cnt;
    double var = (double)sh2[0] / cnt - mean * mean;
    double sc = (double)g[c] * rsqrt(var + 1e-5);
    double sf = (double)b[c] - mean * sc;
    fsc[c] = (float)sc;
    fsf[c] = (float)sf;
    double T = -sf / sc;
    if (sc > 0.0) {
      thr[c] = (int)ceil(T);
      sgn[c] = 1;
    } else {
      thr[c] = (int)floor(T);
      sgn[c] = 0;
    }
  }
}

// --- pack layer: NCHW int16 -> bitpack [pixel][NW] + int8 NHWC [pixel][C] --
__global__ __launch_bounds__(256) void pack_layer_kernel(
    const short* __restrict__ x, const int* __restrict__ thr,
    const int* __restrict__ sgn, uint32_t* __restrict__ apk,
    int8_t* __restrict__ act8, int C, int HW, int NW) {
  int gt = blockIdx.x * 256 + threadIdx.x;
  int lane = gt & 31;
  int gw = gt >> 5;
  int wrd = gw % NW;
  int pixel = (gw / NW) * 32 + lane;
  int n = pixel / HW, hw = pixel % HW;
  const short* base = x + ((size_t)n * C + wrd * 32) * HW + hw;
  const int* tp = thr + wrd * 32;
  const int* sp = sgn + wrd * 32;
  uint32_t bits = 0;
  uint32_t u[8];
#pragma unroll
  for (int j = 0; j < 8; j++) {
    uint32_t uj = 0;
#pragma unroll
    for (int m = 0; m < 4; m++) {
      int k = j * 4 + m;
      int v = base[(size_t)k * HW];
      bool bit = sp[k] ? (v >= tp[k]) : (v <= tp[k]);
      bits |= (bit ? 1u : 0u) << k;
      uj |= (uint32_t)(uint8_t)(bit ? 1 : -1) << (m * 8);
    }
    u[j] = uj;
  }
  apk[(size_t)pixel * NW + wrd] = bits;
  uint4* dst = reinterpret_cast<uint4*>(act8 + (size_t)pixel * C + wrd * 32);
  dst[0] = make_uint4(u[0], u[1], u[2], u[3]);
  dst[1] = make_uint4(u[4], u[5], u[6], u[7]);
}

// ------------- bn + hardtanh: NCHW int16 -> NCHW fp32 ----------------------
__global__ __launch_bounds__(256) void bn_ht_kernel(
    const short* __restrict__ in, const float* __restrict__ fsc,
    const float* __restrict__ fsf, float* __restrict__ out,
    int C, int HW, int total) {
  int idx = blockIdx.x * 256 + threadIdx.x;
  if (idx >= total) return;
  int c = (idx / HW) % C;
  float z = fmaf((float)in[idx], fsc[c], fsf[c]);
  out[idx] = fminf(1.f, fmaxf(-1.f, z));
}

// ----- FC: [256,8192] @ [10,8192]^T + b (TwoProd+Neumaier fp32) ------------
__global__ __launch_bounds__(256) void fc_kernel(
    const float* __restrict__ h, const float* __restrict__ wfc,
    const float* __restrict__ bfc, float* __restrict__ out) {
  int gtid = blockIdx.x * blockDim.x + threadIdx.x;
  int warp = gtid >> 5;
  int lane = gtid & 31;
  if (warp >= 256 * 10) return;
  int n = warp / 10, k = warp % 10;
  const float* hp = h + (size_t)n * 8192;
  const float* wp = wfc + (size_t)k * 8192;
  float s = 0.f, c = 0.f;
  for (int j = lane; j < 8192; j += 32) {
    float a = hp[j], b = wp[j];
    float p = __fmul_rn(a, b);
    float e = __fmaf_rn(a, b, -p);
    two_sum(s, c, p);
    c = __fadd_rn(c, e);
  }
  double d = (double)s + (double)c;
#pragma unroll
  for (int o = 16; o > 0; o >>= 1) d += __shfl_xor_sync(0xFFFFFFFFu, d, o);
  if (lane == 0) out[n * 10 + k] = (float)(d + (double)bfc[k]);
}

// ---------------------------------------------------------------------------
static inline int cdiv(int a, int b) { return (a + b - 1) / b; }

extern "C" void kernel_launch(void* const* d_in, const int* in_sizes, int n_in,
                              void* d_out, int out_size) {
  const float* x   = (const float*)d_in[0];
  const float* w0_ = (const float*)d_in[1];
  const float* g0  = (const float*)d_in[2];
  const float* b0  = (const float*)d_in[3];
  const float* wc1 = (const float*)d_in[4];
  const float* g1  = (const float*)d_in[5];
  const float* b1  = (const float*)d_in[6];
  const float* wc2 = (const float*)d_in[7];
  const float* g2  = (const float*)d_in[8];
  const float* b2  = (const float*)d_in[9];
  const float* wc3 = (const float*)d_in[10];
  const float* g3  = (const float*)d_in[11];
  const float* b3  = (const float*)d_in[12];
  const float* wc4 = (const float*)d_in[13];
  const float* g4  = (const float*)d_in[14];
  const float* b4  = (const float*)d_in[15];
  const float* wc5 = (const float*)d_in[16];
  const float* g5  = (const float*)d_in[17];
  const float* b5  = (const float*)d_in[18];
  const float* wfc = (const float*)d_in[19];
  const float* bfc = (const float*)d_in[20];
  float* out = (float*)d_out;

  float *A, *fsc, *fsf, *fthr;
  short* Cc;
  uint32_t *P, *Wp;
  int8_t *P8, *Wb8;
  int *thr, *sgn, *fsgn;
  cudaGetSymbolAddress((void**)&A, g_A);
  cudaGetSymbolAddress((void**)&Cc, g_C);
  cudaGetSymbolAddress((void**)&P, g_P);
  cudaGetSymbolAddress((void**)&P8, g_P8);
  cudaGetSymbolAddress((void**)&Wp, g_Wp);
  cudaGetSymbolAddress((void**)&Wb8, g_Wb);
  cudaGetSymbolAddress((void**)&fthr, g_fthr);
  cudaGetSymbolAddress((void**)&fsgn, g_fsgn);
  cudaGetSymbolAddress((void**)&thr, g_ithr);
  cudaGetSymbolAddress((void**)&sgn, g_isgn);
  cudaGetSymbolAddress((void**)&fsc, g_fsc);
  cudaGetSymbolAddress((void**)&fsf, g_fsf);
  short* As = (short*)A;
  float* hbuf = (float*)A;

  const int TB = 256;
  const int nI = 104;  // IMMA n-range [0,104); popcount [104,256)

  // 0: conv0; 1: stats0; 2: pack_all; 3: hybrid L1 (profiled slot)
  conv0_kernel<<<256 * 32, TB>>>(x, w0_, A);
  stats0_all<<<128, TB>>>(A, g0, b0, fthr, fsgn);
  pack_all_kernel<<<32768 + 4096 + 558 + 17856, TB>>>(
      A, fthr, fsgn, P8, P, wc1, wc2, wc3, wc4, wc5, Wp, Wb8);

  // L1: 128->128 @32x32 +pool -> Cs
  hybrid_kernel<128, 128, 32, 32, 128, 4, 1, 4, 16, true>
      <<<2048, TB>>>(P, Wp + 0, P8, Wb8 + 0, Cc, 832, 2048, nI);
  stats_int_kernel<<<128, TB>>>(Cc, g1, b1, fsc, fsf, thr, sgn, 256, 128, 256);
  pack_layer_kernel<<<1024, TB>>>(Cc, thr, sgn, P, P8, 128, 256, 4);

  // L2: 128->256 @16x16 -> As
  hybrid_kernel<128, 256, 16, 16, 256, 4, 1, 4, 16, false>
      <<<1024, TB>>>(P, Wp + 4608, P8, Wb8 + 147456, As, 416, 1024, nI);
  stats_int_kernel<<<256, TB>>>(As, g2, b2, fsc, fsf, thr, sgn, 256, 256, 256);
  pack_layer_kernel<<<2048, TB>>>(As, thr, sgn, P, P8, 256, 256, 8);

  // L3: 256->256 @16x16 +pool -> Cs
  hybrid_kernel<256, 256, 16, 16, 128, 8, 2, 4, 16, true>
      <<<1632, TB>>>(P, Wp + 13824, P8, Wb8 + 442368, Cc, 416, 1632, nI);
  stats_int_kernel<<<256, TB>>>(Cc, g3, b3, fsc, fsf, thr, sgn, 256, 256, 64);
  pack_layer_kernel<<<512, TB>>>(Cc, thr, sgn, P, P8, 256, 64, 8);

  // L4: 256->512 @8x8 -> As
  hybrid_kernel<256, 512, 8, 8, 128, 8, 2, 4, 8, false>
      <<<1424, TB>>>(P, Wp + 32256, P8, Wb8 + 1032192, As, 208, 1424, nI);
  stats_int_kernel<<<512, TB>>>(As, g4, b4, fsc, fsf, thr, sgn, 256, 512, 64);
  pack_layer_kernel<<<1024, TB>>>(As, thr, sgn, P, P8, 512, 64, 16);

  // L5: 512->512 @8x8 +pool -> Cs
  hybrid_kernel<512, 512, 8, 8, 64, 16, 4, 4, 8, true>
      <<<2640, TB>>>(P, Wp + 69120, P8, Wb8 + 2211840, Cc, 208, 2640, nI);
  stats_int_kernel<<<512, TB>>>(Cc, g5, b5, fsc, fsf, thr, sgn, 256, 512, 16);

  // bn5 + hardtanh -> hbuf (NCHW fp32), then FC
  bn_ht_kernel<<<cdiv(2097152, TB), TB>>>(Cc, fsc, fsf, hbuf, 512, 16,
                                          2097152);
  fc_kernel<<<cdiv(256 * 10 * 32, TB), TB>>>(hbuf, wfc, bfc, out);
}

// round 10
// speedup vs baseline: 1.4174x; 1.3873x over previous
#include <cuda_runtime.h>
#include <cstdint>
#include <math.h>

// ---------------------------------------------------------------------------
// VGG-small 1w1a forward, batch 256.   (R5 architecture + bconv rotation opt)
// conv0 fp32 -> stats0(comp-fp32, exact fp32 boundary) -> pack0+packw ->
// [bconv popcount (rotation window, fused pool) -> int64 stats -> int pack]x5
// -> bn+ht -> fc
// ---------------------------------------------------------------------------

__device__ __align__(16) float    g_A[33554432];   // conv0 fp32 / int16 NCHW
__device__ __align__(16) float    g_C[8388608];    // pooled int16 NCHW
__device__ __align__(16) uint32_t g_P[1048576];    // bitpacked act [n][y][x][NW]
__device__ __align__(16) uint32_t g_Wp[142848];    // bitpacked weights
__device__ float  g_fthr[512];
__device__ int    g_fsgn[512];
__device__ int    g_ithr[512];
__device__ int    g_isgn[512];
__device__ float  g_fsc[512];
__device__ float  g_fsf[512];

// ---------------- compensated fp32 helpers ---------------------------------
__device__ __forceinline__ void two_sum(float& s, float& c, float v) {
  float t = __fadd_rn(s, v);
  float z = __fsub_rn(t, s);
  float e = __fadd_rn(__fsub_rn(s, __fsub_rn(t, z)), __fsub_rn(v, z));
  s = t;
  c = __fadd_rn(c, e);
}

// ---------------- conv0: fp32 3->128, 32x32, pad 1 -------------------------
__global__ __launch_bounds__(256) void conv0_kernel(
    const float* __restrict__ x, const float* __restrict__ w,
    float* __restrict__ out) {
  __shared__ float sW[128 * 27];
  __shared__ float sX[3][3][34];
  int bx = blockIdx.x;
  int y = bx & 31, n = bx >> 5;
  int tid = threadIdx.x;
  for (int i = tid; i < 3456; i += 256) sW[i] = w[i];
  for (int i = tid; i < 3 * 3 * 34; i += 256) {
    int col = i % 34;
    int r = (i / 34) % 3;
    int ci = i / (34 * 3);
    int gy = y - 1 + r, gx = col - 1;
    float v = 0.f;
    if (gy >= 0 && gy < 32 && gx >= 0 && gx < 32)
      v = x[((n * 3 + ci) * 32 + gy) * 32 + gx];
    sX[ci][r][col] = v;
  }
  __syncthreads();
  int co = tid >> 1, xh = tid & 1, x0 = xh * 16;
  float wr[27];
#pragma unroll
  for (int ky = 0; ky < 3; ky++)
#pragma unroll
    for (int kx = 0; kx < 3; kx++)
#pragma unroll
      for (int ci = 0; ci < 3; ci++)
        wr[(ky * 3 + kx) * 3 + ci] = sW[((co * 3 + ci) * 3 + ky) * 3 + kx];
  float a[3][3][3];
#pragma unroll
  for (int r = 0; r < 3; r++)
#pragma unroll
    for (int ci = 0; ci < 3; ci++) {
      a[r][0][ci] = sX[ci][r][x0];
      a[r][1][ci] = sX[ci][r][x0 + 1];
    }
  float* obase = out + (((size_t)n * 128 + co) * 32 + y) * 32;
#pragma unroll
  for (int xi = 0; xi < 16; xi++) {
    int xc = x0 + xi;
#pragma unroll
    for (int r = 0; r < 3; r++)
#pragma unroll
      for (int ci = 0; ci < 3; ci++) a[r][2][ci] = sX[ci][r][xc + 2];
    float acc = 0.f;
#pragma unroll
    for (int ky = 0; ky < 3; ky++)
#pragma unroll
      for (int kx = 0; kx < 3; kx++)
#pragma unroll
        for (int ci = 0; ci < 3; ci++)
          acc = fmaf(a[ky][kx][ci], wr[(ky * 3 + kx) * 3 + ci], acc);
    obase[xc] = acc;
#pragma unroll
    for (int r = 0; r < 3; r++)
#pragma unroll
      for (int ci = 0; ci < 3; ci++) {
        a[r][0][ci] = a[r][1][ci];
        a[r][1][ci] = a[r][2][ci];
      }
  }
}

// ------- layer0 stats: one block per channel + exact fp32 boundary ---------
__global__ __launch_bounds__(256) void stats0_all(
    const float* __restrict__ x, const float* __restrict__ g,
    const float* __restrict__ b, float* __restrict__ fthr,
    int* __restrict__ fsgn) {
  int c = blockIdx.x;
  float s = 0.f, cs = 0.f, ss = 0.f, css = 0.f;
  for (int n = 0; n < 256; n++) {
    const float* p = x + ((size_t)n * 128 + c) * 1024;
    for (int i = threadIdx.x; i < 1024; i += 256) {
      float v = p[i];
      two_sum(s, cs, v);
      float v2 = __fmul_rn(v, v);
      float e2 = __fmaf_rn(v, v, -v2);
      two_sum(ss, css, v2);
      css = __fadd_rn(css, e2);
    }
  }
  __shared__ double sh1[256], sh2[256];
  sh1[threadIdx.x] = (double)s + (double)cs;
  sh2[threadIdx.x] = (double)ss + (double)css;
  __syncthreads();
  for (int o = 128; o > 0; o >>= 1) {
    if (threadIdx.x < o) {
      sh1[threadIdx.x] += sh1[threadIdx.x + o];
      sh2[threadIdx.x] += sh2[threadIdx.x + o];
    }
    __syncthreads();
  }
  if (threadIdx.x == 0) {
    double cnt = 256.0 * 1024.0;
    double mean = sh1[0] / cnt;
    double var = sh2[0] / cnt - mean * mean;
    double sc = (double)g[c] * rsqrt(var + 1e-5);
    double sf = (double)b[c] - mean * sc;
    if (sc > 0.0) {
      float v = (float)(-sf / sc);
      if (!isfinite(v)) v = 0.f;
      if (fma((double)v, sc, sf) >= 0.0) {
        for (int it = 0; it < 64; it++) {
          float d = nextafterf(v, -INFINITY);
          if (fma((double)d, sc, sf) >= 0.0) v = d; else break;
        }
      } else {
        for (int it = 0; it < 64; it++) {
          v = nextafterf(v, INFINITY);
          if (fma((double)v, sc, sf) >= 0.0) break;
        }
      }
      fthr[c] = v;
      fsgn[c] = 1;
    } else if (sc < 0.0) {
      float v = (float)(-sf / sc);
      if (!isfinite(v)) v = 0.f;
      if (fma((double)v, sc, sf) >= 0.0) {
        for (int it = 0; it < 64; it++) {
          float d = nextafterf(v, INFINITY);
          if (fma((double)d, sc, sf) >= 0.0) v = d; else break;
        }
      } else {
        for (int it = 0; it < 64; it++) {
          v = nextafterf(v, -INFINITY);
          if (fma((double)v, sc, sf) >= 0.0) break;
        }
      }
      fthr[c] = v;
      fsgn[c] = 0;
    } else {
      fthr[c] = (sf >= 0.0) ? -INFINITY : INFINITY;
      fsgn[c] = 1;
    }
  }
}

// ------- fused: pack0 act bitpack + weight bitpack --------------------------
__global__ __launch_bounds__(256) void pack0_packw_kernel(
    const float* __restrict__ x, const float* __restrict__ fthr,
    const int* __restrict__ fsgn, uint32_t* __restrict__ apk,
    const float* __restrict__ w1, const float* __restrict__ w2,
    const float* __restrict__ w3, const float* __restrict__ w4,
    const float* __restrict__ w5, uint32_t* __restrict__ wpk) {
  const int R0 = 4096;
  int tid = threadIdx.x;
  int bx = blockIdx.x;
  if (bx < R0) {
    int gt = bx * 256 + tid;
    int lane = gt & 31;
    int gw = gt >> 5;
    int wrd = gw & 3;
    int pixel = (gw >> 2) * 32 + lane;
    int n = pixel >> 10, hw = pixel & 1023;
    const float* base = x + ((size_t)(n * 128 + wrd * 32)) * 1024 + hw;
    const float* tp = fthr + wrd * 32;
    const int* sp = fsgn + wrd * 32;
    uint32_t bits = 0;
#pragma unroll 8
    for (int k = 0; k < 32; k++) {
      float v = base[(size_t)k * 1024];
      bool bit = sp[k] ? (v >= tp[k]) : (v <= tp[k]);
      bits |= (bit ? 1u : 0u) << k;
    }
    apk[(size_t)pixel * 4 + wrd] = bits;
  } else {
    int idx = (bx - R0) * 256 + tid;
    if (idx >= 142848) return;
    const float* w;
    int Ci, l;
    if (idx < 4608) { w = w1; Ci = 128; l = idx; }
    else if (idx < 13824) { w = w2; Ci = 128; l = idx - 4608; }
    else if (idx < 32256) { w = w3; Ci = 256; l = idx - 13824; }
    else if (idx < 69120) { w = w4; Ci = 256; l = idx - 32256; }
    else { w = w5; Ci = 512; l = idx - 69120; }
    int NW = Ci >> 5;
    int wrd = l % NW;
    int t = l / NW;
    int tap = t % 9;
    int co = t / 9;
    uint32_t bits = 0;
#pragma unroll 8
    for (int k = 0; k < 32; k++) {
      float v = w[((size_t)co * Ci + (wrd * 32 + k)) * 9 + tap];
      bits |= (v >= 0.f ? 1u : 0u) << k;
    }
    wpk[idx] = bits;
  }
}

// ------- binary conv 3x3 pad 1 via XNOR+popcount, rotation window ----------
__device__ __forceinline__ int popc4(uint4 a, uint4 b) {
  return __popc(a.x ^ b.x) + __popc(a.y ^ b.y) +
         __popc(a.z ^ b.z) + __popc(a.w ^ b.w);
}

template <int CO, int CO_G, int H, int W, int NW, int SPLIT, int YT, int XT,
          bool POOL>
__global__ __launch_bounds__(CO_G* SPLIT*(W / XT)) void bconv3_kernel(
    const uint32_t* __restrict__ apk, const uint32_t* __restrict__ wpk,
    short* __restrict__ out) {
  constexpr int NTH = CO_G * SPLIT * (W / XT);
  constexpr int CGRP = CO / CO_G;
  __shared__ uint32_t sW[CO_G * 9 * NW];
  __shared__ uint32_t sA[(YT + 2) * W * NW];
  int bx = blockIdx.x;
  int cg = bx % CGRP;
  int yg = (bx / CGRP) % (H / YT);
  int n = bx / (CGRP * (H / YT));
  int tid = threadIdx.x;
  const uint4* wsrc =
      reinterpret_cast<const uint4*>(wpk + (size_t)cg * CO_G * 9 * NW);
  for (int i = tid; i < CO_G * 9 * NW / 4; i += NTH)
    reinterpret_cast<uint4*>(sW)[i] = wsrc[i];
  int ybase = yg * YT;
  constexpr int RW4 = W * NW / 4;
  for (int i = tid; i < (YT + 2) * RW4; i += NTH) {
    int r = i / RW4;
    int gy = ybase - 1 + r;
    uint4 v = make_uint4(0u, 0u, 0u, 0u);
    if (gy >= 0 && gy < H)
      v = reinterpret_cast<const uint4*>(
          apk + ((size_t)(n * H + gy) * W) * NW)[i % RW4];
    reinterpret_cast<uint4*>(sA)[i] = v;
  }
  __syncthreads();
  int slice = tid % SPLIT;
  int t2 = tid / SPLIT;
  int xg = t2 % (W / XT);
  int co_l = t2 / (W / XT);
  int x0 = xg * XT;
  uint4 wt[9];
#pragma unroll
  for (int t = 0; t < 9; t++)
    wt[t] = *reinterpret_cast<const uint4*>(
        &sW[(co_l * 9 + t) * NW + slice * 4]);
  int co = cg * CO_G + co_l;
  int pmax[XT / 2];
  int tmpv = 0;
#pragma unroll
  for (int ry = 0; ry < YT; ry++) {
    int y = ybase + ry;
    int rv0 = (y > 0) ? 1 : 0;
    int rv2 = (y < H - 1) ? 1 : 0;
    int nrows = 1 + rv0 + rv2;
    // rotation window: win[slot][row]; at xi: L=xi%3, M=(xi+1)%3, R=(xi+2)%3
    uint4 win[3][3];
#pragma unroll
    for (int rr = 0; rr < 3; rr++) {
      win[0][rr] = (x0 > 0)
                       ? *reinterpret_cast<const uint4*>(
                             &sA[((ry + rr) * W + x0 - 1) * NW + slice * 4])
                       : make_uint4(0u, 0u, 0u, 0u);
      win[1][rr] = *reinterpret_cast<const uint4*>(
          &sA[((ry + rr) * W + x0) * NW + slice * 4]);
    }
#pragma unroll
    for (int xi = 0; xi < XT; xi++) {
      const int sL = xi % 3, sM = (xi + 1) % 3, sR = (xi + 2) % 3;
      int xc = x0 + xi;
      int cl = (xc > 0) ? 1 : 0;
      int cr = (xc < W - 1) ? 1 : 0;
#pragma unroll
      for (int rr = 0; rr < 3; rr++)
        win[sR][rr] = cr ? *reinterpret_cast<const uint4*>(
                               &sA[((ry + rr) * W + xc + 1) * NW + slice * 4])
                         : make_uint4(0u, 0u, 0u, 0u);
      int cnt = 0;
#pragma unroll
      for (int rr = 0; rr < 3; rr++) {
        int rvalid = (rr == 0) ? rv0 : ((rr == 2) ? rv2 : 1);
        if (rvalid) {
          if (cl) cnt += popc4(win[sL][rr], wt[rr * 3 + 0]);
          cnt += popc4(win[sM][rr], wt[rr * 3 + 1]);
          if (cr) cnt += popc4(win[sR][rr], wt[rr * 3 + 2]);
        }
      }
#pragma unroll
      for (int o = 1; o < SPLIT; o <<= 1)
        cnt += __shfl_xor_sync(0xffffffffu, cnt, o);
      int ncols = 1 + cl + cr;
      int val = nrows * ncols * 32 * NW - 2 * cnt;
      if (POOL) {
        if ((xi & 1) == 0) {
          tmpv = val;
        } else {
          int m2 = max(tmpv, val);
          if ((ry & 1) == 0) {
            pmax[xi >> 1] = m2;
          } else {
            int m = max(pmax[xi >> 1], m2);
            if (slice == 0)
              out[(((size_t)n * CO + co) * (H / 2) + (y >> 1)) * (W / 2) +
                  (xc >> 1)] = (short)m;
          }
        }
      } else {
        if (slice == 0)
          out[(((size_t)n * CO + co) * H + y) * W + xc] = (short)val;
      }
    }
  }
}

// -------- binary-layer stats: exact int64 accumulation ---------------------
__global__ __launch_bounds__(256) void stats_int_kernel(
    const short* __restrict__ x, const float* __restrict__ g,
    const float* __restrict__ b, float* __restrict__ fsc,
    float* __restrict__ fsf, int* __restrict__ thr, int* __restrict__ sgn,
    int N, int C, int HW) {
  int c = blockIdx.x;
  long long s = 0, ss = 0;
  for (int n = 0; n < N; n++) {
    const short* p = x + ((size_t)n * C + c) * HW;
    for (int i = threadIdx.x; i < HW; i += 256) {
      int v = p[i];
      s += v;
      ss += (long long)(v * v);
    }
  }
  __shared__ long long sh1[256], sh2[256];
  sh1[threadIdx.x] = s;
  sh2[threadIdx.x] = ss;
  __syncthreads();
  for (int o = 128; o > 0; o >>= 1) {
    if (threadIdx.x < o) {
      sh1[threadIdx.x] += sh1[threadIdx.x + o];
      sh2[threadIdx.x] += sh2[threadIdx.x + o];
    }
    __syncthreads();
  }
  if (threadIdx.x == 0) {
    double cnt = (double)N * (double)HW;
    double mean = (double)sh1[0] / cnt;
    double var = (double)sh2[0] / cnt - mean * mean;
    double sc = (double)g[c] * rsqrt(var + 1e-5);
    double sf = (double)b[c] - mean * sc;
    fsc[c] = (float)sc;
    fsf[c] = (float)sf;
    double T = -sf / sc;
    if (sc > 0.0) {
      thr[c] = (int)ceil(T);
      sgn[c] = 1;
    } else {
      thr[c] = (int)floor(T);
      sgn[c] = 0;
    }
  }
}

// -------- binary-layer pack: pure integer predicate ------------------------
__global__ __launch_bounds__(256) void pack_int_kernel(
    const short* __restrict__ x, const int* __restrict__ thr,
    const int* __restrict__ sgn, uint32_t* __restrict__ apk,
    int C, int HW, int NW) {
  int gt = blockIdx.x * 256 + threadIdx.x;
  int lane = gt & 31;
  int gw = gt >> 5;
  int wrd = gw % NW;
  int chunk = gw / NW;
  int pixel = chunk * 32 + lane;
  int n = pixel / HW, hw = pixel % HW;
  const short* base = x + ((size_t)n * C + wrd * 32) * HW + hw;
  const int* tp = thr + wrd * 32;
  const int* sp = sgn + wrd * 32;
  uint32_t bits = 0;
#pragma unroll 8
  for (int k = 0; k < 32; k++) {
    int v = base[(size_t)k * HW];
    bool bit = sp[k] ? (v >= tp[k]) : (v <= tp[k]);
    bits |= (bit ? 1u : 0u) << k;
  }
  apk[(size_t)pixel * NW + wrd] = bits;
}

// ------------- bn + hardtanh (fp32 continuous path) ------------------------
__global__ __launch_bounds__(256) void bn_ht_kernel(
    const short* __restrict__ in, const float* __restrict__ fsc,
    const float* __restrict__ fsf, float* __restrict__ out,
    int C, int HW, int total) {
  int idx = blockIdx.x * 256 + threadIdx.x;
  if (idx >= total) return;
  int c = (idx / HW) % C;
  float z = fmaf((float)in[idx], fsc[c], fsf[c]);
  out[idx] = fminf(1.f, fmaxf(-1.f, z));
}

// ----- FC: [256,8192] @ [10,8192]^T + b (TwoProd+Neumaier fp32) ------------
__global__ __launch_bounds__(256) void fc_kernel(
    const float* __restrict__ h, const float* __restrict__ wfc,
    const float* __restrict__ bfc, float* __restrict__ out) {
  int gtid = blockIdx.x * blockDim.x + threadIdx.x;
  int warp = gtid >> 5;
  int lane = gtid & 31;
  if (warp >= 256 * 10) return;
  int n = warp / 10, k = warp % 10;
  const float* hp = h + (size_t)n * 8192;
  const float* wp = wfc + (size_t)k * 8192;
  float s = 0.f, c = 0.f;
  for (int j = lane; j < 8192; j += 32) {
    float a = hp[j], b = wp[j];
    float p = __fmul_rn(a, b);
    float e = __fmaf_rn(a, b, -p);
    two_sum(s, c, p);
    c = __fadd_rn(c, e);
  }
  double d = (double)s + (double)c;
#pragma unroll
  for (int o = 16; o > 0; o >>= 1) d += __shfl_xor_sync(0xFFFFFFFFu, d, o);
  if (lane == 0) out[n * 10 + k] = (float)(d + (double)bfc[k]);
}

// ---------------------------------------------------------------------------
static inline int cdiv(int a, int b) { return (a + b - 1) / b; }

extern "C" void kernel_launch(void* const* d_in, const int* in_sizes, int n_in,
                              void* d_out, int out_size) {
  const float* x   = (const float*)d_in[0];
  const float* w0_ = (const float*)d_in[1];
  const float* g0  = (const float*)d_in[2];
  const float* b0  = (const float*)d_in[3];
  const float* wc1 = (const float*)d_in[4];
  const float* g1  = (const float*)d_in[5];
  const float* b1  = (const float*)d_in[6];
  const float* wc2 = (const float*)d_in[7];
  const float* g2  = (const float*)d_in[8];
  const float* b2  = (const float*)d_in[9];
  const float* wc3 = (const float*)d_in[10];
  const float* g3  = (const float*)d_in[11];
  const float* b3  = (const float*)d_in[12];
  const float* wc4 = (const float*)d_in[13];
  const float* g4  = (const float*)d_in[14];
  const float* b4  = (const float*)d_in[15];
  const float* wc5 = (const float*)d_in[16];
  const float* g5  = (const float*)d_in[17];
  const float* b5  = (const float*)d_in[18];
  const float* wfc = (const float*)d_in[19];
  const float* bfc = (const float*)d_in[20];
  float* out = (float*)d_out;

  float *A, *Cb, *fsc, *fsf, *fthr;
  uint32_t *P, *Wp;
  int *thr, *sgn, *fsgn;
  cudaGetSymbolAddress((void**)&A, g_A);
  cudaGetSymbolAddress((void**)&Cb, g_C);
  cudaGetSymbolAddress((void**)&P, g_P);
  cudaGetSymbolAddress((void**)&Wp, g_Wp);
  cudaGetSymbolAddress((void**)&fthr, g_fthr);
  cudaGetSymbolAddress((void**)&fsgn, g_fsgn);
  cudaGetSymbolAddress((void**)&thr, g_ithr);
  cudaGetSymbolAddress((void**)&sgn, g_isgn);
  cudaGetSymbolAddress((void**)&fsc, g_fsc);
  cudaGetSymbolAddress((void**)&fsf, g_fsf);
  short* As = (short*)A;
  short* Cs = (short*)Cb;
  float* hbuf = (float*)A;

  const int N = 256;
  const int TB = 256;

  // 0: conv0; 1: stats0; 2: pack0+packw; 3: bconv L1 (profiled slot)
  conv0_kernel<<<N * 32, TB>>>(x, w0_, A);
  stats0_all<<<128, TB>>>(A, g0, b0, fthr, fsgn);
  pack0_packw_kernel<<<4096 + 558, TB>>>(A, fthr, fsgn, P, wc1, wc2, wc3,
                                         wc4, wc5, Wp);

  // L1: 128->128 @32 +pool -> Cs
  bconv3_kernel<128, 128, 32, 32, 4, 1, 4, 16, true>
      <<<N * 8, TB>>>(P, Wp + 0, Cs);
  stats_int_kernel<<<128, TB>>>(Cs, g1, b1, fsc, fsf, thr, sgn, N, 128, 256);
  pack_int_kernel<<<N * 256 * 4 / TB, TB>>>(Cs, thr, sgn, P, 128, 256, 4);

  // L2: 128->256 @16 -> As
  bconv3_kernel<256, 256, 16, 16, 4, 1, 4, 16, false>
      <<<N * 4, TB>>>(P, Wp + 4608, As);
  stats_int_kernel<<<256, TB>>>(As, g2, b2, fsc, fsf, thr, sgn, N, 256, 256);
  pack_int_kernel<<<N * 256 * 8 / TB, TB>>>(As, thr, sgn, P, 256, 256, 8);

  // L3: 256->256 @16 +pool -> Cs
  bconv3_kernel<256, 128, 16, 16, 8, 2, 4, 16, true>
      <<<N * 8, TB>>>(P, Wp + 13824, Cs);
  stats_int_kernel<<<256, TB>>>(Cs, g3, b3, fsc, fsf, thr, sgn, N, 256, 64);
  pack_int_kernel<<<N * 64 * 8 / TB, TB>>>(Cs, thr, sgn, P, 256, 64, 8);

  // L4: 256->512 @8 -> As
  bconv3_kernel<512, 128, 8, 8, 8, 2, 4, 8, false>
      <<<N * 8, TB>>>(P, Wp + 32256, As);
  stats_int_kernel<<<512, TB>>>(As, g4, b4, fsc, fsf, thr, sgn, N, 512, 64);
  pack_int_kernel<<<N * 64 * 16 / TB, TB>>>(As, thr, sgn, P, 512, 64, 16);

  // L5: 512->512 @8 +pool -> Cs
  bconv3_kernel<512, 64, 8, 8, 16, 4, 4, 8, true>
      <<<N * 16, TB>>>(P, Wp + 69120, Cs);
  stats_int_kernel<<<512, TB>>>(Cs, g5, b5, fsc, fsf, thr, sgn, N, 512, 16);

  // bn5 + hardtanh -> hbuf, then FC
  bn_ht_kernel<<<cdiv(2097152, TB), TB>>>(Cs, fsc, fsf, hbuf, 512, 16,
                                          2097152);
  fc_kernel<<<cdiv(N * 10 * 32, TB), TB>>>(hbuf, wfc, bfc, out);
}

// round 12
// speedup vs baseline: 1.4214x; 1.0028x over previous
#include <cuda_runtime.h>
#include <cstdint>
#include <math.h>

// ---------------------------------------------------------------------------
// VGG-small 1w1a forward, batch 256.
// conv0 fp32 -> stats0(comp-fp32, exact fp32 boundary) -> pack0+packw ->
// [bconv popcount (row-wise taps, low-register rotation) -> int stats ->
//  int pack] x5 -> bn+ht -> fc
// ---------------------------------------------------------------------------

__device__ __align__(16) float    g_A[33554432];   // conv0 fp32 / int16 NCHW
__device__ __align__(16) float    g_C[8388608];    // pooled int16 NCHW
__device__ __align__(16) uint32_t g_P[1048576];    // bitpacked act [n][y][x][NW]
__device__ __align__(16) uint32_t g_Wp[142848];    // bitpacked weights
__device__ float  g_fthr[512];
__device__ int    g_fsgn[512];
__device__ int    g_ithr[512];
__device__ int    g_isgn[512];
__device__ float  g_fsc[512];
__device__ float  g_fsf[512];

// ---------------- compensated fp32 helpers ---------------------------------
__device__ __forceinline__ void two_sum(float& s, float& c, float v) {
  float t = __fadd_rn(s, v);
  float z = __fsub_rn(t, s);
  float e = __fadd_rn(__fsub_rn(s, __fsub_rn(t, z)), __fsub_rn(v, z));
  s = t;
  c = __fadd_rn(c, e);
}

// ---------------- conv0: fp32 3->128, 32x32, pad 1 -------------------------
__global__ __launch_bounds__(256) void conv0_kernel(
    const float* __restrict__ x, const float* __restrict__ w,
    float* __restrict__ out) {
  __shared__ float sW[128 * 27];
  __shared__ float sX[3][3][34];
  int bx = blockIdx.x;
  int y = bx & 31, n = bx >> 5;
  int tid = threadIdx.x;
  for (int i = tid; i < 3456; i += 256) sW[i] = w[i];
  for (int i = tid; i < 3 * 3 * 34; i += 256) {
    int col = i % 34;
    int r = (i / 34) % 3;
    int ci = i / (34 * 3);
    int gy = y - 1 + r, gx = col - 1;
    float v = 0.f;
    if (gy >= 0 && gy < 32 && gx >= 0 && gx < 32)
      v = x[((n * 3 + ci) * 32 + gy) * 32 + gx];
    sX[ci][r][col] = v;
  }
  __syncthreads();
  int co = tid >> 1, xh = tid & 1, x0 = xh * 16;
  float wr[27];
#pragma unroll
  for (int ky = 0; ky < 3; ky++)
#pragma unroll
    for (int kx = 0; kx < 3; kx++)
#pragma unroll
      for (int ci = 0; ci < 3; ci++)
        wr[(ky * 3 + kx) * 3 + ci] = sW[((co * 3 + ci) * 3 + ky) * 3 + kx];
  float a[3][3][3];
#pragma unroll
  for (int r = 0; r < 3; r++)
#pragma unroll
    for (int ci = 0; ci < 3; ci++) {
      a[r][0][ci] = sX[ci][r][x0];
      a[r][1][ci] = sX[ci][r][x0 + 1];
    }
  float* obase = out + (((size_t)n * 128 + co) * 32 + y) * 32;
#pragma unroll
  for (int xi = 0; xi < 16; xi++) {
    int xc = x0 + xi;
#pragma unroll
    for (int r = 0; r < 3; r++)
#pragma unroll
      for (int ci = 0; ci < 3; ci++) a[r][2][ci] = sX[ci][r][xc + 2];
    float acc = 0.f;
#pragma unroll
    for (int ky = 0; ky < 3; ky++)
#pragma unroll
      for (int kx = 0; kx < 3; kx++)
#pragma unroll
        for (int ci = 0; ci < 3; ci++)
          acc = fmaf(a[ky][kx][ci], wr[(ky * 3 + kx) * 3 + ci], acc);
    obase[xc] = acc;
#pragma unroll
    for (int r = 0; r < 3; r++)
#pragma unroll
      for (int ci = 0; ci < 3; ci++) {
        a[r][0][ci] = a[r][1][ci];
        a[r][1][ci] = a[r][2][ci];
      }
  }
}

// ------- layer0 stats: one block per channel + exact fp32 boundary ---------
__global__ __launch_bounds__(256) void stats0_all(
    const float* __restrict__ x, const float* __restrict__ g,
    const float* __restrict__ b, float* __restrict__ fthr,
    int* __restrict__ fsgn) {
  int c = blockIdx.x;
  float s = 0.f, cs = 0.f, ss = 0.f, css = 0.f;
  for (int n = 0; n < 256; n++) {
    const float* p = x + ((size_t)n * 128 + c) * 1024;
    for (int i = threadIdx.x; i < 1024; i += 256) {
      float v = p[i];
      two_sum(s, cs, v);
      float v2 = __fmul_rn(v, v);
      float e2 = __fmaf_rn(v, v, -v2);
      two_sum(ss, css, v2);
      css = __fadd_rn(css, e2);
    }
  }
  __shared__ double sh1[256], sh2[256];
  sh1[threadIdx.x] = (double)s + (double)cs;
  sh2[threadIdx.x] = (double)ss + (double)css;
  __syncthreads();
  for (int o = 128; o > 0; o >>= 1) {
    if (threadIdx.x < o) {
      sh1[threadIdx.x] += sh1[threadIdx.x + o];
      sh2[threadIdx.x] += sh2[threadIdx.x + o];
    }
    __syncthreads();
  }
  if (threadIdx.x == 0) {
    double cnt = 256.0 * 1024.0;
    double mean = sh1[0] / cnt;
    double var = sh2[0] / cnt - mean * mean;
    double sc = (double)g[c] * rsqrt(var + 1e-5);
    double sf = (double)b[c] - mean * sc;
    if (sc > 0.0) {
      float v = (float)(-sf / sc);
      if (!isfinite(v)) v = 0.f;
      if (fma((double)v, sc, sf) >= 0.0) {
        for (int it = 0; it < 64; it++) {
          float d = nextafterf(v, -INFINITY);
          if (fma((double)d, sc, sf) >= 0.0) v = d; else break;
        }
      } else {
        for (int it = 0; it < 64; it++) {
          v = nextafterf(v, INFINITY);
          if (fma((double)v, sc, sf) >= 0.0) break;
        }
      }
      fthr[c] = v;
      fsgn[c] = 1;
    } else if (sc < 0.0) {
      float v = (float)(-sf / sc);
      if (!isfinite(v)) v = 0.f;
      if (fma((double)v, sc, sf) >= 0.0) {
        for (int it = 0; it < 64; it++) {
          float d = nextafterf(v, INFINITY);
          if (fma((double)d, sc, sf) >= 0.0) v = d; else break;
        }
      } else {
        for (int it = 0; it < 64; it++) {
          v = nextafterf(v, -INFINITY);
          if (fma((double)v, sc, sf) >= 0.0) break;
        }
      }
      fthr[c] = v;
      fsgn[c] = 0;
    } else {
      fthr[c] = (sf >= 0.0) ? -INFINITY : INFINITY;
      fsgn[c] = 1;
    }
  }
}

// ------- fused: pack0 act bitpack + weight bitpack --------------------------
__global__ __launch_bounds__(256) void pack0_packw_kernel(
    const float* __restrict__ x, const float* __restrict__ fthr,
    const int* __restrict__ fsgn, uint32_t* __restrict__ apk,
    const float* __restrict__ w1, const float* __restrict__ w2,
    const float* __restrict__ w3, const float* __restrict__ w4,
    const float* __restrict__ w5, uint32_t* __restrict__ wpk) {
  const int R0 = 4096;
  int tid = threadIdx.x;
  int bx = blockIdx.x;
  if (bx < R0) {
    int gt = bx * 256 + tid;
    int lane = gt & 31;
    int gw = gt >> 5;
    int wrd = gw & 3;
    int pixel = (gw >> 2) * 32 + lane;
    int n = pixel >> 10, hw = pixel & 1023;
    const float* base = x + ((size_t)(n * 128 + wrd * 32)) * 1024 + hw;
    const float* tp = fthr + wrd * 32;
    const int* sp = fsgn + wrd * 32;
    uint32_t bits = 0;
#pragma unroll 8
    for (int k = 0; k < 32; k++) {
      float v = base[(size_t)k * 1024];
      bool bit = sp[k] ? (v >= tp[k]) : (v <= tp[k]);
      bits |= (bit ? 1u : 0u) << k;
    }
    apk[(size_t)pixel * 4 + wrd] = bits;
  } else {
    int idx = (bx - R0) * 256 + tid;
    if (idx >= 142848) return;
    const float* w;
    int Ci, l;
    if (idx < 4608) { w = w1; Ci = 128; l = idx; }
    else if (idx < 13824) { w = w2; Ci = 128; l = idx - 4608; }
    else if (idx < 32256) { w = w3; Ci = 256; l = idx - 13824; }
    else if (idx < 69120) { w = w4; Ci = 256; l = idx - 32256; }
    else { w = w5; Ci = 512; l = idx - 69120; }
    int NW = Ci >> 5;
    int wrd = l % NW;
    int t = l / NW;
    int tap = t % 9;
    int co = t / 9;
    uint32_t bits = 0;
#pragma unroll 8
    for (int k = 0; k < 32; k++) {
      float v = w[((size_t)co * Ci + (wrd * 32 + k)) * 9 + tap];
      bits |= (v >= 0.f ? 1u : 0u) << k;
    }
    wpk[idx] = bits;
  }
}

// ------- binary conv 3x3 pad 1, row-wise taps, low-register ----------------
__device__ __forceinline__ int popc4(uint4 a, uint4 b) {
  return __popc(a.x ^ b.x) + __popc(a.y ^ b.y) +
         __popc(a.z ^ b.z) + __popc(a.w ^ b.w);
}

template <int CO, int CO_G, int H, int W, int NW, int SPLIT, int YT, int XT,
          bool POOL>
__global__ __launch_bounds__(CO_G* SPLIT*(W / XT), 2) void bconv5_kernel(
    const uint32_t* __restrict__ apk, const uint32_t* __restrict__ wpk,
    short* __restrict__ out) {
  constexpr int NTH = CO_G * SPLIT * (W / XT);
  constexpr int CGRP = CO / CO_G;
  __shared__ uint32_t sW[CO_G * 9 * NW];
  __shared__ uint32_t sA[(YT + 2) * W * NW];
  int bx = blockIdx.x;
  int cg = bx % CGRP;
  int yg = (bx / CGRP) % (H / YT);
  int n = bx / (CGRP * (H / YT));
  int tid = threadIdx.x;
  const uint4* wsrc =
      reinterpret_cast<const uint4*>(wpk + (size_t)cg * CO_G * 9 * NW);
  for (int i = tid; i < CO_G * 9 * NW / 4; i += NTH)
    reinterpret_cast<uint4*>(sW)[i] = wsrc[i];
  int ybase = yg * YT;
  constexpr int RW4 = W * NW / 4;
  for (int i = tid; i < (YT + 2) * RW4; i += NTH) {
    int r = i / RW4;
    int gy = ybase - 1 + r;
    uint4 v = make_uint4(0u, 0u, 0u, 0u);
    if (gy >= 0 && gy < H)
      v = reinterpret_cast<const uint4*>(
          apk + ((size_t)(n * H + gy) * W) * NW)[i % RW4];
    reinterpret_cast<uint4*>(sA)[i] = v;
  }
  __syncthreads();
  int slice = tid % SPLIT;
  int t2 = tid / SPLIT;
  int xg = t2 % (W / XT);
  int co_l = t2 / (W / XT);
  int x0 = xg * XT;
  int co = cg * CO_G + co_l;
  int pmax[XT / 2];
  int tmpv = 0;
#pragma unroll
  for (int ry = 0; ry < YT; ry++) {
    int y = ybase + ry;
    int rv0 = (y > 0) ? 1 : 0;
    int rv2 = (y < H - 1) ? 1 : 0;
    int nrows = 1 + rv0 + rv2;
    int cnt[XT];
#pragma unroll
    for (int xi = 0; xi < XT; xi++) cnt[xi] = 0;
    // row-wise: only one kernel-row's taps + 3-slot window live at a time
#pragma unroll
    for (int rr = 0; rr < 3; rr++) {
      int rvalid = (rr == 0) ? rv0 : ((rr == 2) ? rv2 : 1);
      if (rvalid) {
        uint4 w0 = *reinterpret_cast<const uint4*>(
            &sW[(co_l * 9 + rr * 3 + 0) * NW + slice * 4]);
        uint4 w1 = *reinterpret_cast<const uint4*>(
            &sW[(co_l * 9 + rr * 3 + 1) * NW + slice * 4]);
        uint4 w2 = *reinterpret_cast<const uint4*>(
            &sW[(co_l * 9 + rr * 3 + 2) * NW + slice * 4]);
        const uint32_t* row = &sA[(ry + rr) * W * NW + slice * 4];
        uint4 win[3];
        win[0] = (x0 > 0)
                     ? *reinterpret_cast<const uint4*>(&row[(x0 - 1) * NW])
                     : make_uint4(0u, 0u, 0u, 0u);
        win[1] = *reinterpret_cast<const uint4*>(&row[x0 * NW]);
#pragma unroll
        for (int xi = 0; xi < XT; xi++) {
          const int sL = xi % 3, sM = (xi + 1) % 3, sR = (xi + 2) % 3;
          int xc = x0 + xi;
          int cl = (xc > 0) ? 1 : 0;
          int cr = (xc < W - 1) ? 1 : 0;
          win[sR] = cr ? *reinterpret_cast<const uint4*>(&row[(xc + 1) * NW])
                       : make_uint4(0u, 0u, 0u, 0u);
          int c = 0;
          if (cl) c += popc4(win[sL], w0);
          c += popc4(win[sM], w1);
          if (cr) c += popc4(win[sR], w2);
          cnt[xi] += c;
        }
      }
    }
    // epilogue for this output row
#pragma unroll
    for (int xi = 0; xi < XT; xi++) {
      int xc = x0 + xi;
      int cl = (xc > 0) ? 1 : 0;
      int cr = (xc < W - 1) ? 1 : 0;
      int c = cnt[xi];
#pragma unroll
      for (int o = 1; o < SPLIT; o <<= 1)
        c += __shfl_xor_sync(0xffffffffu, c, o);
      int ncols = 1 + cl + cr;
      int val = nrows * ncols * 32 * NW - 2 * c;
      if (POOL) {
        if ((xi & 1) == 0) {
          tmpv = val;
        } else {
          int m2 = max(tmpv, val);
          if ((ry & 1) == 0) {
            pmax[xi >> 1] = m2;
          } else {
            int m = max(pmax[xi >> 1], m2);
            if (slice == 0)
              out[(((size_t)n * CO + co) * (H / 2) + (y >> 1)) * (W / 2) +
                  (xc >> 1)] = (short)m;
          }
        }
      } else {
        if (slice == 0)
          out[(((size_t)n * CO + co) * H + y) * W + xc] = (short)val;
      }
    }
  }
}

// -------- binary-layer stats: exact int64 accumulation ---------------------
__global__ __launch_bounds__(256) void stats_int_kernel(
    const short* __restrict__ x, const float* __restrict__ g,
    const float* __restrict__ b, float* __restrict__ fsc,
    float* __restrict__ fsf, int* __restrict__ thr, int* __restrict__ sgn,
    int N, int C, int HW) {
  int c = blockIdx.x;
  long long s = 0, ss = 0;
  for (int n = 0; n < N; n++) {
    const short* p = x + ((size_t)n * C + c) * HW;
    for (int i = threadIdx.x; i < HW; i += 256) {
      int v = p[i];
      s += v;
      ss += (long long)(v * v);
    }
  }
  __shared__ long long sh1[256], sh2[256];
  sh1[threadIdx.x] = s;
  sh2[threadIdx.x] = ss;
  __syncthreads();
  for (int o = 128; o > 0; o >>= 1) {
    if (threadIdx.x < o) {
      sh1[threadIdx.x] += sh1[threadIdx.x + o];
      sh2[threadIdx.x] += sh2[threadIdx.x + o];
    }
    __syncthreads();
  }
  if (threadIdx.x == 0) {
    double cnt = (double)N * (double)HW;
    double mean = (double)sh1[0] / cnt;
    double var = (double)sh2[0] / cnt - mean * mean;
    double sc = (double)g[c] * rsqrt(var + 1e-5);
    double sf = (double)b[c] - mean * sc;
    fsc[c] = (float)sc;
    fsf[c] = (float)sf;
    double T = -sf / sc;
    if (sc > 0.0) {
      thr[c] = (int)ceil(T);
      sgn[c] = 1;
    } else {
      thr[c] = (int)floor(T);
      sgn[c] = 0;
    }
  }
}

// -------- binary-layer pack: pure integer predicate ------------------------
__global__ __launch_bounds__(256) void pack_int_kernel(
    const short* __restrict__ x, const int* __restrict__ thr,
    const int* __restrict__ sgn, uint32_t* __restrict__ apk,
    int C, int HW, int NW) {
  int gt = blockIdx.x * 256 + threadIdx.x;
  int lane = gt & 31;
  int gw = gt >> 5;
  int wrd = gw % NW;
  int chunk = gw / NW;
  int pixel = chunk * 32 + lane;
  int n = pixel / HW, hw = pixel % HW;
  const short* base = x + ((size_t)n * C + wrd * 32) * HW + hw;
  const int* tp = thr + wrd * 32;
  const int* sp = sgn + wrd * 32;
  uint32_t bits = 0;
#pragma unroll 8
  for (int k = 0; k < 32; k++) {
    int v = base[(size_t)k * HW];
    bool bit = sp[k] ? (v >= tp[k]) : (v <= tp[k]);
    bits |= (bit ? 1u : 0u) << k;
  }
  apk[(size_t)pixel * NW + wrd] = bits;
}

// ------------- bn + hardtanh (fp32 continuous path) ------------------------
__global__ __launch_bounds__(256) void bn_ht_kernel(
    const short* __restrict__ in, const float* __restrict__ fsc,
    const float* __restrict__ fsf, float* __restrict__ out,
    int C, int HW, int total) {
  int idx = blockIdx.x * 256 + threadIdx.x;
  if (idx >= total) return;
  int c = (idx / HW) % C;
  float z = fmaf((float)in[idx], fsc[c], fsf[c]);
  out[idx] = fminf(1.f, fmaxf(-1.f, z));
}

// ----- FC: [256,8192] @ [10,8192]^T + b (TwoProd+Neumaier fp32) ------------
__global__ __launch_bounds__(256) void fc_kernel(
    const float* __restrict__ h, const float* __restrict__ wfc,
    const float* __restrict__ bfc, float* __restrict__ out) {
  int gtid = blockIdx.x * blockDim.x + threadIdx.x;
  int warp = gtid >> 5;
  int lane = gtid & 31;
  if (warp >= 256 * 10) return;
  int n = warp / 10, k = warp % 10;
  const float* hp = h + (size_t)n * 8192;
  const float* wp = wfc + (size_t)k * 8192;
  float s = 0.f, c = 0.f;
  for (int j = lane; j < 8192; j += 32) {
    float a = hp[j], b = wp[j];
    float p = __fmul_rn(a, b);
    float e = __fmaf_rn(a, b, -p);
    two_sum(s, c, p);
    c = __fadd_rn(c, e);
  }
  double d = (double)s + (double)c;
#pragma unroll
  for (int o = 16; o > 0; o >>= 1) d += __shfl_xor_sync(0xFFFFFFFFu, d, o);
  if (lane == 0) out[n * 10 + k] = (float)(d + (double)bfc[k]);
}

// ---------------------------------------------------------------------------
static inline int cdiv(int a, int b) { return (a + b - 1) / b; }

extern "C" void kernel_launch(void* const* d_in, const int* in_sizes, int n_in,
                              void* d_out, int out_size) {
  const float* x   = (const float*)d_in[0];
  const float* w0_ = (const float*)d_in[1];
  const float* g0  = (const float*)d_in[2];
  const float* b0  = (const float*)d_in[3];
  const float* wc1 = (const float*)d_in[4];
  const float* g1  = (const float*)d_in[5];
  const float* b1  = (const float*)d_in[6];
  const float* wc2 = (const float*)d_in[7];
  const float* g2  = (const float*)d_in[8];
  const float* b2  = (const float*)d_in[9];
  const float* wc3 = (const float*)d_in[10];
  const float* g3  = (const float*)d_in[11];
  const float* b3  = (const float*)d_in[12];
  const float* wc4 = (const float*)d_in[13];
  const float* g4  = (const float*)d_in[14];
  const float* b4  = (const float*)d_in[15];
  const float* wc5 = (const float*)d_in[16];
  const float* g5  = (const float*)d_in[17];
  const float* b5  = (const float*)d_in[18];
  const float* wfc = (const float*)d_in[19];
  const float* bfc = (const float*)d_in[20];
  float* out = (float*)d_out;

  float *A, *Cb, *fsc, *fsf, *fthr;
  uint32_t *P, *Wp;
  int *thr, *sgn, *fsgn;
  cudaGetSymbolAddress((void**)&A, g_A);
  cudaGetSymbolAddress((void**)&Cb, g_C);
  cudaGetSymbolAddress((void**)&P, g_P);
  cudaGetSymbolAddress((void**)&Wp, g_Wp);
  cudaGetSymbolAddress((void**)&fthr, g_fthr);
  cudaGetSymbolAddress((void**)&fsgn, g_fsgn);
  cudaGetSymbolAddress((void**)&thr, g_ithr);
  cudaGetSymbolAddress((void**)&sgn, g_isgn);
  cudaGetSymbolAddress((void**)&fsc, g_fsc);
  cudaGetSymbolAddress((void**)&fsf, g_fsf);
  short* As = (short*)A;
  short* Cs = (short*)Cb;
  float* hbuf = (float*)A;

  const int N = 256;
  const int TB = 256;

  // 0: conv0; 1: stats0; 2: pack0+packw; 3: bconv L1 (profiled slot)
  conv0_kernel<<<N * 32, TB>>>(x, w0_, A);
  stats0_all<<<128, TB>>>(A, g0, b0, fthr, fsgn);
  pack0_packw_kernel<<<4096 + 558, TB>>>(A, fthr, fsgn, P, wc1, wc2, wc3,
                                         wc4, wc5, Wp);

  // L1: 128->128 @32 +pool -> Cs
  bconv5_kernel<128, 128, 32, 32, 4, 1, 4, 16, true>
      <<<N * 8, TB>>>(P, Wp + 0, Cs);
  stats_int_kernel<<<128, TB>>>(Cs, g1, b1, fsc, fsf, thr, sgn, N, 128, 256);
  pack_int_kernel<<<N * 256 * 4 / TB, TB>>>(Cs, thr, sgn, P, 128, 256, 4);

  // L2: 128->256 @16 -> As
  bconv5_kernel<256, 256, 16, 16, 4, 1, 4, 16, false>
      <<<N * 4, TB>>>(P, Wp + 4608, As);
  stats_int_kernel<<<256, TB>>>(As, g2, b2, fsc, fsf, thr, sgn, N, 256, 256);
  pack_int_kernel<<<N * 256 * 8 / TB, TB>>>(As, thr, sgn, P, 256, 256, 8);

  // L3: 256->256 @16 +pool -> Cs
  bconv5_kernel<256, 128, 16, 16, 8, 2, 4, 16, true>
      <<<N * 8, TB>>>(P, Wp + 13824, Cs);
  stats_int_kernel<<<256, TB>>>(Cs, g3, b3, fsc, fsf, thr, sgn, N, 256, 64);
  pack_int_kernel<<<N * 64 * 8 / TB, TB>>>(Cs, thr, sgn, P, 256, 64, 8);

  // L4: 256->512 @8 -> As
  bconv5_kernel<512, 128, 8, 8, 8, 2, 4, 8, false>
      <<<N * 8, TB>>>(P, Wp + 32256, As);
  stats_int_kernel<<<512, TB>>>(As, g4, b4, fsc, fsf, thr, sgn, N, 512, 64);
  pack_int_kernel<<<N * 64 * 16 / TB, TB>>>(As, thr, sgn, P, 512, 64, 16);

  // L5: 512->512 @8 +pool -> Cs
  bconv5_kernel<512, 64, 8, 8, 16, 4, 4, 8, true>
      <<<N * 16, TB>>>(P, Wp + 69120, Cs);
  stats_int_kernel<<<512, TB>>>(Cs, g5, b5, fsc, fsf, thr, sgn, N, 512, 16);

  // bn5 + hardtanh -> hbuf, then FC
  bn_ht_kernel<<<cdiv(2097152, TB), TB>>>(Cs, fsc, fsf, hbuf, 512, 16,
                                          2097152);
  fc_kernel<<<cdiv(N * 10 * 32, TB), TB>>>(hbuf, wfc, bfc, out);
}